// round 12
// baseline (speedup 1.0000x reference)
#include <cuda_runtime.h>
#include <cuda_bf16.h>
#include <cstdint>

// ---------------------------------------------------------------- constants
#define EPSV      1e-5f
#define SCALE_QK  0.17677669529663687f   // 1/sqrt(32)

#define BB   64
#define NN   784
#define NQ   196
#define CC   512
#define HH   16
#define OKV  1536
#define OQ   512
#define DH   1024
#define OP   768
#define MKV  (BB*NN)  // 50176
#define MQ   (BB*NQ)  // 12544

// ---------------------------------------------------------------- scratch
__device__ float g_Ykv[(size_t)MKV * OKV];
__device__ float g_Yq [(size_t)MQ  * OQ];
__device__ float g_Yp [(size_t)MQ  * OP];
__device__ float g_ps [(size_t)(BB * 14) * OKV];   // up to 896 chunk partials
__device__ float g_pq [(size_t)(BB * 14) * OKV];
__device__ float g_sc_kv[OKV], g_sh_kv[OKV];
__device__ float g_sc_q [OQ],  g_sh_q [OQ];
__device__ float g_sc_p [OP],  g_sh_p [OP];

// bf16 split operands
__device__ __nv_bfloat16 g_xh [(size_t)MKV * CC],  g_xl [(size_t)MKV * CC];
__device__ __nv_bfloat16 g_Wkvh[(size_t)OKV * CC], g_Wkvl[(size_t)OKV * CC];
__device__ __nv_bfloat16 g_Wqh [(size_t)OQ  * CC], g_Wql [(size_t)OQ  * CC];
__device__ __nv_bfloat16 g_Wph [(size_t)OP  * DH], g_Wpl [(size_t)OP  * DH];
__device__ __nv_bfloat16 g_Yoh [(size_t)MQ  * DH], g_Yol [(size_t)MQ  * DH];

// prepped attention operands (RAW values, bf16 split; V transposed)
__device__ __nv_bfloat16 g_KH [(size_t)BB * HH * NN * 32], g_KL [(size_t)BB * HH * NN * 32];
__device__ __nv_bfloat16 g_VTH[(size_t)BB * HH * 64 * NN], g_VTL[(size_t)BB * HH * 64 * NN];

// ---------------------------------------------------------------- helpers
__device__ __forceinline__ uint32_t smem_u32(const void* p) {
    uint32_t a;
    asm("{ .reg .u64 t; cvta.to.shared.u64 t, %1; cvt.u32.u64 %0, t; }" : "=r"(a) : "l"(p));
    return a;
}
__device__ __forceinline__ void cp_async16(uint32_t dst, const void* src) {
    asm volatile("cp.async.cg.shared.global [%0], [%1], 16;" :: "r"(dst), "l"(src) : "memory");
}
__device__ __forceinline__ void cp_commit() {
    asm volatile("cp.async.commit_group;" ::: "memory");
}
template<int N>
__device__ __forceinline__ void cp_wait() {
    asm volatile("cp.async.wait_group %0;" :: "n"(N) : "memory");
}
__device__ __forceinline__ void mma16816(float* c, uint32_t a0, uint32_t a1,
                                         uint32_t a2, uint32_t a3,
                                         uint32_t b0, uint32_t b1) {
    asm volatile(
        "mma.sync.aligned.m16n8k16.row.col.f32.bf16.bf16.f32 "
        "{%0,%1,%2,%3}, {%4,%5,%6,%7}, {%8,%9}, {%0,%1,%2,%3};"
        : "+f"(c[0]), "+f"(c[1]), "+f"(c[2]), "+f"(c[3])
        : "r"(a0), "r"(a1), "r"(a2), "r"(a3), "r"(b0), "r"(b1));
}
__device__ __forceinline__ void ldsm_x4(uint32_t addr, uint32_t& r0, uint32_t& r1,
                                        uint32_t& r2, uint32_t& r3) {
    asm volatile("ldmatrix.sync.aligned.m8n8.x4.shared.b16 {%0,%1,%2,%3}, [%4];"
        : "=r"(r0), "=r"(r1), "=r"(r2), "=r"(r3) : "r"(addr));
}
__device__ __forceinline__ void ldsm_x2(uint32_t addr, uint32_t& r0, uint32_t& r1) {
    asm volatile("ldmatrix.sync.aligned.m8n8.x2.shared.b16 {%0,%1}, [%2];"
        : "=r"(r0), "=r"(r1) : "r"(addr));
}

// ---------------------------------------------------------------- fp32 -> bf16 hi/lo split
__global__ void __launch_bounds__(256) cvt_split4(
    const float* __restrict__ X, __nv_bfloat16* __restrict__ H,
    __nv_bfloat16* __restrict__ L, size_t n4)
{
    size_t i = (size_t)blockIdx.x * 256 + threadIdx.x;
    if (i >= n4) return;
    float4 v = reinterpret_cast<const float4*>(X)[i];
    __nv_bfloat16 hx = __float2bfloat16(v.x);
    __nv_bfloat16 hy = __float2bfloat16(v.y);
    __nv_bfloat16 hz = __float2bfloat16(v.z);
    __nv_bfloat16 hw = __float2bfloat16(v.w);
    __nv_bfloat16 lx = __float2bfloat16(v.x - __bfloat162float(hx));
    __nv_bfloat16 ly = __float2bfloat16(v.y - __bfloat162float(hy));
    __nv_bfloat16 lz = __float2bfloat16(v.z - __bfloat162float(hz));
    __nv_bfloat16 lw = __float2bfloat16(v.w - __bfloat162float(hw));
    reinterpret_cast<__nv_bfloat162*>(H)[2 * i]     = __halves2bfloat162(hx, hy);
    reinterpret_cast<__nv_bfloat162*>(H)[2 * i + 1] = __halves2bfloat162(hz, hw);
    reinterpret_cast<__nv_bfloat162*>(L)[2 * i]     = __halves2bfloat162(lx, ly);
    reinterpret_cast<__nv_bfloat162*>(L)[2 * i + 1] = __halves2bfloat162(lz, lw);
}

// ---------------------------------------------------------------- mma.sync bf16-split GEMM
// Single-barrier mainloop: wait -> sync -> issue(c+1) -> compute(c).
#define LDA_B    80
#define MAT_B    (128 * LDA_B)
#define STAGE_B  (4 * MAT_B)
#define GEMM_SMEM (2 * STAGE_B)

template<int GATHER>
__device__ __forceinline__ void load_chunk(
    const __nv_bfloat16* __restrict__ Ah_g, const __nv_bfloat16* __restrict__ Al_g,
    const __nv_bfloat16* __restrict__ Bh_g, const __nv_bfloat16* __restrict__ Bl_g,
    uint32_t sbase, int mBase, int nBase, int k0, int K, int tid)
{
    #pragma unroll
    for (int i = 0; i < 8; i++) {
        int u = tid + i * 256;
        int mat = u >> 9;
        int r   = (u >> 2) & 127;
        int seg = u & 3;
        const __nv_bfloat16* src;
        int row;
        if (mat < 2) {
            row = mBase + r;
            if (GATHER) {
                int bb = row / 196;
                int t  = row - bb * 196;
                row = bb * 784 + (t / 14) * 56 + (t % 14) * 2;
            }
            src = (mat == 0) ? Ah_g : Al_g;
        } else {
            row = nBase + r;
            src = (mat == 2) ? Bh_g : Bl_g;
        }
        cp_async16(sbase + mat * MAT_B + r * LDA_B + seg * 16,
                   src + (size_t)row * K + k0 + seg * 8);
    }
}

__device__ __forceinline__ void compute_chunk(
    uint32_t stage, float acc[2][8][4], int wm, int wn, int lane)
{
    const int sub    = lane >> 3;
    const int arow_f = (lane & 7) + ((sub & 1) << 3);
    const int akof   = (sub >> 1) << 3;
    const int brow_f = lane & 7;
    const int bkof   = ((lane >> 3) & 1) << 3;

    #pragma unroll
    for (int ks = 0; ks < 2; ks++) {
        const int kb = ks * 16;
        uint32_t Ahf[2][4], Alf[2][4];
        #pragma unroll
        for (int mt = 0; mt < 2; mt++) {
            uint32_t aaddr = stage + (uint32_t)(wm + mt * 16 + arow_f) * LDA_B
                           + (uint32_t)(kb + akof) * 2;
            ldsm_x4(aaddr,         Ahf[mt][0], Ahf[mt][1], Ahf[mt][2], Ahf[mt][3]);
            ldsm_x4(aaddr + MAT_B, Alf[mt][0], Alf[mt][1], Alf[mt][2], Alf[mt][3]);
        }
        #pragma unroll
        for (int nt = 0; nt < 8; nt++) {
            uint32_t baddr = stage + 2 * MAT_B + (uint32_t)(wn + nt * 8 + brow_f) * LDA_B
                           + (uint32_t)(kb + bkof) * 2;
            uint32_t bh0, bh1, bl0, bl1;
            ldsm_x2(baddr,         bh0, bh1);
            ldsm_x2(baddr + MAT_B, bl0, bl1);
            #pragma unroll
            for (int mt = 0; mt < 2; mt++) {
                mma16816(acc[mt][nt], Ahf[mt][0], Ahf[mt][1], Ahf[mt][2], Ahf[mt][3], bh0, bh1);
                mma16816(acc[mt][nt], Ahf[mt][0], Ahf[mt][1], Ahf[mt][2], Ahf[mt][3], bl0, bl1);
                mma16816(acc[mt][nt], Alf[mt][0], Alf[mt][1], Alf[mt][2], Alf[mt][3], bh0, bh1);
            }
        }
    }
}

template<int GATHER>
__global__ void __launch_bounds__(256) gemm_mma(
    const __nv_bfloat16* __restrict__ Ah_g, const __nv_bfloat16* __restrict__ Al_g,
    const __nv_bfloat16* __restrict__ Bh_g, const __nv_bfloat16* __restrict__ Bl_g,
    float* __restrict__ C, int M, int N, int K)
{
    extern __shared__ char gsm[];
    const int tid = threadIdx.x;
    const int wid = tid >> 5, lane = tid & 31;
    const int mBase = blockIdx.y * 128;
    const int nBase = blockIdx.x * 128;
    const int wm = (wid & 3) * 32;
    const int wn = (wid >> 2) * 64;

    const uint32_t sbase = smem_u32(gsm);

    float acc[2][8][4];
    #pragma unroll
    for (int mt = 0; mt < 2; mt++)
        #pragma unroll
        for (int nt = 0; nt < 8; nt++)
            #pragma unroll
            for (int j = 0; j < 4; j++) acc[mt][nt][j] = 0.f;

    const int nc = K >> 5;

    load_chunk<GATHER>(Ah_g, Al_g, Bh_g, Bl_g, sbase, mBase, nBase, 0, K, tid);
    cp_commit();

    for (int c = 0; c < nc; c++) {
        cp_wait<0>();
        __syncthreads();
        if (c + 1 < nc) {
            load_chunk<GATHER>(Ah_g, Al_g, Bh_g, Bl_g,
                               sbase + ((c + 1) & 1) * STAGE_B,
                               mBase, nBase, (c + 1) * 32, K, tid);
            cp_commit();
        }
        compute_chunk(sbase + (c & 1) * STAGE_B, acc, wm, wn, lane);
    }

    const uint32_t g  = lane >> 2;
    const uint32_t t4 = lane & 3;
    #pragma unroll
    for (int mt = 0; mt < 2; mt++) {
        #pragma unroll
        for (int nt = 0; nt < 8; nt++) {
            const int col = nBase + wn + nt * 8 + t4 * 2;
            const int r0 = mBase + wm + mt * 16 + g;
            float2 v0 = make_float2(acc[mt][nt][0], acc[mt][nt][1]);
            float2 v1 = make_float2(acc[mt][nt][2], acc[mt][nt][3]);
            *reinterpret_cast<float2*>(C + (size_t)r0 * N + col)       = v0;
            *reinterpret_cast<float2*>(C + (size_t)(r0 + 8) * N + col) = v1;
        }
    }
}

// ---------------------------------------------------------------- column reduce (partial, 64 chunks)
__global__ void __launch_bounds__(256) col_partial(
    const float* __restrict__ Y, float* __restrict__ ps, float* __restrict__ pq,
    int M, int Ncols)
{
    const int col = blockIdx.x * 256 + threadIdx.x;
    const int ch  = blockIdx.y;
    const int per = (M + 63) >> 6;
    const int r0 = ch * per;
    int r1 = r0 + per; if (r1 > M) r1 = M;
    float s = 0.f, s2 = 0.f;
    for (int r = r0; r < r1; r++) {
        float v = Y[(size_t)r * Ncols + col];
        s += v;
        s2 = fmaf(v, v, s2);
    }
    ps[(size_t)ch * Ncols + col] = s;
    pq[(size_t)ch * Ncols + col] = s2;
}

// ---------------------------------------------------------------- BN finalize (nch chunks)
__global__ void __launch_bounds__(256) bn_finalize(
    const float* __restrict__ ps, const float* __restrict__ pq,
    const float* __restrict__ g, const float* __restrict__ b,
    float* __restrict__ scale, float* __restrict__ shift,
    int Ncols, int nch, float invM)
{
    const int col = blockIdx.x * 256 + threadIdx.x;
    float s = 0.f, s2 = 0.f;
    for (int c = 0; c < nch; c++) {
        s  += ps[(size_t)c * Ncols + col];
        s2 += pq[(size_t)c * Ncols + col];
    }
    float m   = s * invM;
    float var = s2 * invM - m * m;
    float sc  = g[col] * rsqrtf(var + EPSV);
    scale[col] = sc;
    shift[col] = b[col] - m * sc;
}

// ---------------------------------------------------------------- K/V prep (raw split + transpose) + fused column stats
__global__ void __launch_bounds__(256) prep_kv(
    const float* __restrict__ Ykv,
    __nv_bfloat16* __restrict__ KH, __nv_bfloat16* __restrict__ KL,
    __nv_bfloat16* __restrict__ VTH, __nv_bfloat16* __restrict__ VTL,
    float* __restrict__ ps, float* __restrict__ pq)
{
    __shared__ __align__(16) __nv_bfloat16 sVh[64 * 56];
    __shared__ __align__(16) __nv_bfloat16 sVl[64 * 56];
    __shared__ float pS[10][96], pQ[10][96];

    const int tid = threadIdx.x;
    const int kc = blockIdx.x, h = blockIdx.y, b = blockIdx.z;
    const int kb = kc * 56;
    const int bh = b * HH + h;

    const int f = tid % 24;    // float4 index within 96 channels
    const int rg = tid / 24;   // row group 0..9 (tid>=240 idle)

    if (rg < 10) {
        float s4[4] = {0.f, 0.f, 0.f, 0.f};
        float q4[4] = {0.f, 0.f, 0.f, 0.f};
        for (int r = rg; r < 56; r += 10) {
            float4 v = *(reinterpret_cast<const float4*>(
                Ykv + (size_t)(b * NN + kb + r) * OKV + h * 96) + f);
            float vv[4] = {v.x, v.y, v.z, v.w};
            #pragma unroll
            for (int j = 0; j < 4; j++) {
                s4[j] += vv[j];
                q4[j] = fmaf(vv[j], vv[j], q4[j]);
            }
            if (f < 8) {
                int d = f * 4;
                __nv_bfloat16 hh[4], ll[4];
                #pragma unroll
                for (int j = 0; j < 4; j++) {
                    hh[j] = __float2bfloat16(vv[j]);
                    ll[j] = __float2bfloat16(vv[j] - __bfloat162float(hh[j]));
                }
                size_t base = ((size_t)bh * NN + kb + r) * 32 + d;
                reinterpret_cast<__nv_bfloat162*>(KH + base)[0] = __halves2bfloat162(hh[0], hh[1]);
                reinterpret_cast<__nv_bfloat162*>(KH + base)[1] = __halves2bfloat162(hh[2], hh[3]);
                reinterpret_cast<__nv_bfloat162*>(KL + base)[0] = __halves2bfloat162(ll[0], ll[1]);
                reinterpret_cast<__nv_bfloat162*>(KL + base)[1] = __halves2bfloat162(ll[2], ll[3]);
            } else {
                int d = (f - 8) * 4;
                #pragma unroll
                for (int j = 0; j < 4; j++) {
                    __nv_bfloat16 hh = __float2bfloat16(vv[j]);
                    sVh[(d + j) * 56 + r] = hh;
                    sVl[(d + j) * 56 + r] = __float2bfloat16(vv[j] - __bfloat162float(hh));
                }
            }
        }
        #pragma unroll
        for (int j = 0; j < 4; j++) { pS[rg][f * 4 + j] = s4[j]; pQ[rg][f * 4 + j] = q4[j]; }
    }
    __syncthreads();

    // stats writeout
    if (tid < 96) {
        float s = 0.f, q = 0.f;
        #pragma unroll
        for (int gi = 0; gi < 10; gi++) { s += pS[gi][tid]; q += pQ[gi][tid]; }
        size_t chunk = (size_t)(b * 14 + kc);
        ps[chunk * OKV + h * 96 + tid] = s;
        pq[chunk * OKV + h * 96 + tid] = q;
    }

    // V transposed writeout
    for (int u = tid; u < 64 * 7; u += 256) {
        int d = u / 7, seg = u - d * 7;
        uint4 vh = *reinterpret_cast<const uint4*>(&sVh[d * 56 + seg * 8]);
        uint4 vl = *reinterpret_cast<const uint4*>(&sVl[d * 56 + seg * 8]);
        size_t base = ((size_t)bh * 64 + d) * NN + kb + seg * 8;
        *reinterpret_cast<uint4*>(VTH + base) = vh;
        *reinterpret_cast<uint4*>(VTL + base) = vl;
    }
}

// ---------------------------------------------------------------- attention (tensor-core, raw K/V, folded BN)
__device__ __forceinline__ float hswish(float x) {
    float t = fminf(fmaxf(x + 3.f, 0.f), 6.f);
    return x * t * (1.f / 6.f);
}

// smem byte offsets
#define AQP 80
#define AVP 144
#define K_ST 4480
#define V_ST 9216
#define O_QH 0
#define O_QL 5120
#define O_KH 10240
#define O_KL 19200
#define O_VH 28160
#define O_VL 46592
#define O_PH 65024
#define O_PL 74240
#define O_S  83456
#define O_BH 94432
#define O_SCQ 97568
#define O_SHQ 97696
#define O_SCK 97824
#define O_SCV 97952
#define O_SHV 98208
#define O_MR 98464
#define O_LR 98720
#define O_AR 98976
#define ATTN_SMEM 99232

__global__ void __launch_bounds__(256) attn_mma2(
    const __nv_bfloat16* __restrict__ KHg, const __nv_bfloat16* __restrict__ KLg,
    const __nv_bfloat16* __restrict__ VTHg, const __nv_bfloat16* __restrict__ VTLg,
    const float* __restrict__ Yq,
    const float* __restrict__ scq,  const float* __restrict__ shq,
    const float* __restrict__ sckv, const float* __restrict__ shkv,
    const float* __restrict__ biases, const int* __restrict__ bidx,
    __nv_bfloat16* __restrict__ Yoh, __nv_bfloat16* __restrict__ Yol)
{
    extern __shared__ char sm[];
    __nv_bfloat16* Qh = reinterpret_cast<__nv_bfloat16*>(sm + O_QH);
    __nv_bfloat16* Ql = reinterpret_cast<__nv_bfloat16*>(sm + O_QL);
    __nv_bfloat16* Ph = reinterpret_cast<__nv_bfloat16*>(sm + O_PH);
    __nv_bfloat16* Pl = reinterpret_cast<__nv_bfloat16*>(sm + O_PL);
    float* S    = reinterpret_cast<float*>(sm + O_S);
    float* bh   = reinterpret_cast<float*>(sm + O_BH);
    float* scqh = reinterpret_cast<float*>(sm + O_SCQ);
    float* shqh = reinterpret_cast<float*>(sm + O_SHQ);
    float* sckh = reinterpret_cast<float*>(sm + O_SCK);
    float* scvh = reinterpret_cast<float*>(sm + O_SCV);
    float* shvh = reinterpret_cast<float*>(sm + O_SHV);
    float* mrow = reinterpret_cast<float*>(sm + O_MR);
    float* lrow = reinterpret_cast<float*>(sm + O_LR);
    float* arow = reinterpret_cast<float*>(sm + O_AR);

    const int tid = threadIdx.x;
    const int wid = tid >> 5, lane = tid & 31;
    const int qg = blockIdx.x, h = blockIdx.y, b = blockIdx.z;
    const int bh_idx = b * HH + h;

    const __nv_bfloat16* KHb = KHg + (size_t)bh_idx * NN * 32;
    const __nv_bfloat16* KLb = KLg + (size_t)bh_idx * NN * 32;
    const __nv_bfloat16* VHb = VTHg + (size_t)bh_idx * 64 * NN;
    const __nv_bfloat16* VLb = VTLg + (size_t)bh_idx * 64 * NN;

    const uint32_t sbase = smem_u32(sm);
    const uint32_t uQH = sbase + O_QH, uQL = sbase + O_QL;
    const uint32_t uKH = sbase + O_KH, uKL = sbase + O_KL;
    const uint32_t uVH = sbase + O_VH, uVL = sbase + O_VL;
    const uint32_t uPH = sbase + O_PH, uPL = sbase + O_PL;

    // ---- init: per-head constants, bias, stats, pad-zeroing
    if (tid < 32) {
        scqh[tid] = scq[h * 32 + tid];
        shqh[tid] = shq[h * 32 + tid];
        sckh[tid] = sckv[h * 96 + tid];
    } else if (tid < 96) {
        int d = tid - 32;
        scvh[d] = sckv[h * 96 + 32 + d];
        shvh[d] = shkv[h * 96 + 32 + d];
    }
    for (int i = tid; i < 784; i += 256) bh[i] = biases[h * 784 + i];
    if (tid < 64) { mrow[tid] = -1e30f; lrow[tid] = 0.f; arow[tid] = 0.f; }
    // zero Q rows 49..63 (both mats)
    for (int u = tid; u < 150; u += 256) {
        int m = u / 75, w = u - m * 75;
        int r = 49 + w / 5, sgm = w - (w / 5) * 5;
        uint32_t off = (m == 0 ? O_QH : O_QL) + (uint32_t)r * AQP + sgm * 16;
        *reinterpret_cast<uint4*>(sm + off) = make_uint4(0, 0, 0, 0);
    }
    // zero V pad cols (bytes 112..143) both stages/mats
    for (int u = tid; u < 512; u += 256) {
        int m = u >> 8, w = u & 255;
        int st = w >> 7, w2 = w & 127;
        int d = w2 >> 1, half = w2 & 1;
        uint32_t off = (m == 0 ? O_VH : O_VL) + st * V_ST + (uint32_t)d * AVP + 112 + half * 16;
        *reinterpret_cast<uint4*>(sm + off) = make_uint4(0, 0, 0, 0);
    }
    // zero P region
    for (int u = tid; u < 1152; u += 256)
        reinterpret_cast<uint4*>(sm + O_PH)[u] = make_uint4(0, 0, 0, 0);
    __syncthreads();

    // Q tile fill: q'' = (scq*q + shq) * sck
    for (int e = tid; e < 49 * 32; e += 256) {
        int r = e >> 5, d = e & 31;
        float v = fmaf(Yq[(size_t)(b * NQ + qg * 49 + r) * OQ + h * 32 + d], scqh[d], shqh[d]) * sckh[d];
        __nv_bfloat16 hh = __float2bfloat16(v);
        Qh[r * 40 + d] = hh;
        Ql[r * 40 + d] = __float2bfloat16(v - __bfloat162float(hh));
    }

    // ---- cp.async chunk loader
    auto issue_chunk = [&](int kc) {
        const int st = kc & 1;
        const int kb = kc * 56;
        #pragma unroll
        for (int i = 0; i < 6; i++) {
            int u = tid + i * 256;
            if (u >= 1344) break;
            if (u < 448) {
                int hi = (u < 224);
                int w = hi ? u : u - 224;
                int r = w >> 2, seg = w & 3;
                const __nv_bfloat16* src = (hi ? KHb : KLb) + (size_t)(kb + r) * 32 + seg * 8;
                uint32_t dst = (hi ? uKH : uKL) + st * K_ST + (uint32_t)r * AQP + seg * 16;
                cp_async16(dst, src);
            } else {
                int v = u - 448;
                int hi = (v < 448);
                int w = hi ? v : v - 448;
                int d = w / 7, seg = w - d * 7;
                const __nv_bfloat16* src = (hi ? VHb : VLb) + (size_t)d * NN + kb + seg * 8;
                uint32_t dst = (hi ? uVH : uVL) + st * V_ST + (uint32_t)d * AVP + seg * 16;
                cp_async16(dst, src);
            }
        }
        cp_commit();
    };

    // fragment mapping
    const int mw  = wid >> 1;
    const int nt0 = (wid & 1) * 4;
    const int ntn = (wid & 1) ? 3 : 4;
    const int g   = lane >> 2, t4 = lane & 3;
    const int sub = lane >> 3;
    const int arow_f = (lane & 7) + ((sub & 1) << 3);
    const int akof   = (sub >> 1) << 3;
    const int brow_f = lane & 7;
    const int bkof   = ((lane >> 3) & 1) << 3;
    const int sr = (tid < 196) ? (tid >> 2) : 48;
    const int sq = tid & 3;
    const bool sact = (tid < 196);

    float accp[4][4];
    #pragma unroll
    for (int i = 0; i < 4; i++)
        #pragma unroll
        for (int j = 0; j < 4; j++) accp[i][j] = 0.f;

    issue_chunk(0);

    for (int kc = 0; kc < 14; kc++) {
        const int st = kc & 1;
        const int kb = kc * 56;

        cp_wait<0>();
        __syncthreads();

        if (kc + 1 < 14) issue_chunk(kc + 1);

        // ---- QK mma + bias + write S
        {
            float acc[4][4];
            #pragma unroll
            for (int i = 0; i < 4; i++)
                #pragma unroll
                for (int j = 0; j < 4; j++) acc[i][j] = 0.f;
            #pragma unroll
            for (int ks = 0; ks < 2; ks++) {
                uint32_t aoff = (uint32_t)(mw * 16 + arow_f) * AQP + (uint32_t)(ks * 16 + akof) * 2;
                uint32_t Ahf[4], Alf[4];
                ldsm_x4(uQH + aoff, Ahf[0], Ahf[1], Ahf[2], Ahf[3]);
                ldsm_x4(uQL + aoff, Alf[0], Alf[1], Alf[2], Alf[3]);
                for (int nti = 0; nti < ntn; nti++) {
                    int nt = nt0 + nti;
                    uint32_t boff = st * K_ST + (uint32_t)(nt * 8 + brow_f) * AQP
                                  + (uint32_t)(ks * 16 + bkof) * 2;
                    uint32_t bh0, bh1, bl0, bl1;
                    ldsm_x2(uKH + boff, bh0, bh1);
                    ldsm_x2(uKL + boff, bl0, bl1);
                    mma16816(acc[nti], Ahf[0], Ahf[1], Ahf[2], Ahf[3], bh0, bh1);
                    mma16816(acc[nti], Ahf[0], Ahf[1], Ahf[2], Ahf[3], bl0, bl1);
                    mma16816(acc[nti], Alf[0], Alf[1], Alf[2], Alf[3], bh0, bh1);
                }
            }
            const int r0 = mw * 16 + g;
            for (int nti = 0; nti < ntn; nti++) {
                int nt = nt0 + nti;
                int c0 = nt * 8 + t4 * 2;
                if (r0 < 49) {
                    int2 id = *reinterpret_cast<const int2*>(
                        &bidx[(size_t)(qg * 49 + r0) * NN + kb + c0]);
                    float2 s0 = make_float2(fmaf(acc[nti][0], SCALE_QK, bh[id.x]),
                                            fmaf(acc[nti][1], SCALE_QK, bh[id.y]));
                    *reinterpret_cast<float2*>(&S[r0 * 56 + c0]) = s0;
                }
                if (r0 + 8 < 49) {
                    int2 id = *reinterpret_cast<const int2*>(
                        &bidx[(size_t)(qg * 49 + r0 + 8) * NN + kb + c0]);
                    float2 s1 = make_float2(fmaf(acc[nti][2], SCALE_QK, bh[id.x]),
                                            fmaf(acc[nti][3], SCALE_QK, bh[id.y]));
                    *reinterpret_cast<float2*>(&S[(r0 + 8) * 56 + c0]) = s1;
                }
            }
        }
        __syncthreads();

        // ---- online softmax, write P bf16 hi/lo
        {
            float xv[14];
            float cm = -1e30f;
            #pragma unroll
            for (int j = 0; j < 14; j++) {
                xv[j] = S[sr * 56 + sq + 4 * j];
                cm = fmaxf(cm, xv[j]);
            }
            cm = fmaxf(cm, __shfl_xor_sync(0xffffffffu, cm, 1));
            cm = fmaxf(cm, __shfl_xor_sync(0xffffffffu, cm, 2));
            float mo = mrow[sr];
            float mn = fmaxf(mo, cm);
            float cs = 0.f;
            #pragma unroll
            for (int j = 0; j < 14; j++) {
                float p = __expf(xv[j] - mn);
                xv[j] = p;
                cs += p;
            }
            cs += __shfl_xor_sync(0xffffffffu, cs, 1);
            cs += __shfl_xor_sync(0xffffffffu, cs, 2);
            if (sact) {
                #pragma unroll
                for (int j = 0; j < 14; j++) {
                    __nv_bfloat16 ph = __float2bfloat16(xv[j]);
                    Ph[sr * 72 + sq + 4 * j] = ph;
                    Pl[sr * 72 + sq + 4 * j] = __float2bfloat16(xv[j] - __bfloat162float(ph));
                }
                if (sq == 0) {
                    float a = __expf(mo - mn);
                    arow[sr] = a;
                    lrow[sr] = lrow[sr] * a + cs;
                    mrow[sr] = mn;
                }
            }
        }
        __syncthreads();

        // ---- PV mma with rescale
        {
            const int r0 = mw * 16 + g;
            float a0 = arow[r0], a1 = arow[r0 + 8];
            #pragma unroll
            for (int nti = 0; nti < 4; nti++) {
                accp[nti][0] *= a0; accp[nti][1] *= a0;
                accp[nti][2] *= a1; accp[nti][3] *= a1;
            }
            #pragma unroll
            for (int ks = 0; ks < 4; ks++) {
                uint32_t aoff = (uint32_t)(mw * 16 + arow_f) * AVP + (uint32_t)(ks * 16 + akof) * 2;
                uint32_t Phf[4], Plf[4];
                ldsm_x4(uPH + aoff, Phf[0], Phf[1], Phf[2], Phf[3]);
                ldsm_x4(uPL + aoff, Plf[0], Plf[1], Plf[2], Plf[3]);
                #pragma unroll
                for (int nti = 0; nti < 4; nti++) {
                    int dt8 = ((wid & 1) * 4 + nti) * 8;
                    uint32_t boff = st * V_ST + (uint32_t)(dt8 + brow_f) * AVP
                                  + (uint32_t)(ks * 16 + bkof) * 2;
                    uint32_t vh0, vh1, vl0, vl1;
                    ldsm_x2(uVH + boff, vh0, vh1);
                    ldsm_x2(uVL + boff, vl0, vl1);
                    mma16816(accp[nti], Phf[0], Phf[1], Phf[2], Phf[3], vh0, vh1);
                    mma16816(accp[nti], Phf[0], Phf[1], Phf[2], Phf[3], vl0, vl1);
                    mma16816(accp[nti], Plf[0], Plf[1], Plf[2], Plf[3], vh0, vh1);
                }
            }
        }
    }

    // ---- epilogue: out = hswish(scv * acc/l + shv), bf16 hi/lo store
    const int r0 = mw * 16 + g;
    #pragma unroll
    for (int half = 0; half < 2; half++) {
        int rr = r0 + half * 8;
        if (rr >= 49) continue;
        float inv = 1.0f / lrow[rr];
        int q = qg * 49 + rr;
        #pragma unroll
        for (int nti = 0; nti < 4; nti++) {
            int c0 = (wid & 1) * 32 + nti * 8 + t4 * 2;
            float o0 = hswish(fmaf(accp[nti][half * 2 + 0] * inv, scvh[c0],     shvh[c0]));
            float o1 = hswish(fmaf(accp[nti][half * 2 + 1] * inv, scvh[c0 + 1], shvh[c0 + 1]));
            __nv_bfloat16 h0 = __float2bfloat16(o0);
            __nv_bfloat16 h1 = __float2bfloat16(o1);
            __nv_bfloat16 l0 = __float2bfloat16(o0 - __bfloat162float(h0));
            __nv_bfloat16 l1 = __float2bfloat16(o1 - __bfloat162float(h1));
            size_t base = (size_t)(b * NQ + q) * DH + h * 64 + c0;
            *reinterpret_cast<__nv_bfloat162*>(Yoh + base) = __halves2bfloat162(h0, h1);
            *reinterpret_cast<__nv_bfloat162*>(Yol + base) = __halves2bfloat162(l0, l1);
        }
    }
}

// ---------------------------------------------------------------- final BN apply (float4)
__global__ void __launch_bounds__(256) bn_apply4(
    const float4* __restrict__ Y, const float* __restrict__ scale,
    const float* __restrict__ shift, float4* __restrict__ out, int Ncols4)
{
    const int i = blockIdx.x * 256 + threadIdx.x;
    float4 v = Y[i];
    const int c = (i % Ncols4) * 4;
    out[i] = make_float4(fmaf(v.x, scale[c + 0], shift[c + 0]),
                         fmaf(v.y, scale[c + 1], shift[c + 1]),
                         fmaf(v.z, scale[c + 2], shift[c + 2]),
                         fmaf(v.w, scale[c + 3], shift[c + 3]));
}

// ---------------------------------------------------------------- launch
extern "C" void kernel_launch(void* const* d_in, const int* in_sizes, int n_in,
                              void* d_out, int out_size)
{
    const float* x    = (const float*)d_in[0];
    const float* W_kv = (const float*)d_in[1];
    const float* gkv  = (const float*)d_in[2];
    const float* bkv  = (const float*)d_in[3];
    const float* W_q  = (const float*)d_in[4];
    const float* gq   = (const float*)d_in[5];
    const float* bq   = (const float*)d_in[6];
    const float* W_p  = (const float*)d_in[7];
    const float* gp   = (const float*)d_in[8];
    const float* bp   = (const float*)d_in[9];
    const float* ab   = (const float*)d_in[10];
    const int*   bidx = (const int*)d_in[11];
    float* out = (float*)d_out;

    float *Ykv, *Yq, *Yp, *ps, *pq;
    float *sckv, *shkv, *scq, *shq, *scp, *shp;
    __nv_bfloat16 *xh, *xl, *Wkvh, *Wkvl, *Wqh, *Wql, *Wph, *Wpl, *Yoh, *Yol;
    __nv_bfloat16 *KH, *KL, *VTH, *VTL;
    cudaGetSymbolAddress((void**)&Ykv, g_Ykv);
    cudaGetSymbolAddress((void**)&Yq,  g_Yq);
    cudaGetSymbolAddress((void**)&Yp,  g_Yp);
    cudaGetSymbolAddress((void**)&ps,  g_ps);
    cudaGetSymbolAddress((void**)&pq,  g_pq);
    cudaGetSymbolAddress((void**)&sckv, g_sc_kv);
    cudaGetSymbolAddress((void**)&shkv, g_sh_kv);
    cudaGetSymbolAddress((void**)&scq,  g_sc_q);
    cudaGetSymbolAddress((void**)&shq,  g_sh_q);
    cudaGetSymbolAddress((void**)&scp,  g_sc_p);
    cudaGetSymbolAddress((void**)&shp,  g_sh_p);
    cudaGetSymbolAddress((void**)&xh,   g_xh);
    cudaGetSymbolAddress((void**)&xl,   g_xl);
    cudaGetSymbolAddress((void**)&Wkvh, g_Wkvh);
    cudaGetSymbolAddress((void**)&Wkvl, g_Wkvl);
    cudaGetSymbolAddress((void**)&Wqh,  g_Wqh);
    cudaGetSymbolAddress((void**)&Wql,  g_Wql);
    cudaGetSymbolAddress((void**)&Wph,  g_Wph);
    cudaGetSymbolAddress((void**)&Wpl,  g_Wpl);
    cudaGetSymbolAddress((void**)&Yoh,  g_Yoh);
    cudaGetSymbolAddress((void**)&Yol,  g_Yol);
    cudaGetSymbolAddress((void**)&KH,   g_KH);
    cudaGetSymbolAddress((void**)&KL,   g_KL);
    cudaGetSymbolAddress((void**)&VTH,  g_VTH);
    cudaGetSymbolAddress((void**)&VTL,  g_VTL);

    cudaFuncSetAttribute(gemm_mma<0>, cudaFuncAttributeMaxDynamicSharedMemorySize, GEMM_SMEM);
    cudaFuncSetAttribute(gemm_mma<1>, cudaFuncAttributeMaxDynamicSharedMemorySize, GEMM_SMEM);
    cudaFuncSetAttribute(attn_mma2, cudaFuncAttributeMaxDynamicSharedMemorySize, ATTN_SMEM);

    // 0) bf16 hi/lo splits
    cvt_split4<<<(unsigned)(((size_t)MKV * CC / 4 + 255) / 256), 256>>>(x, xh, xl, (size_t)MKV * CC / 4);
    cvt_split4<<<(unsigned)(((size_t)OKV * CC / 4 + 255) / 256), 256>>>(W_kv, Wkvh, Wkvl, (size_t)OKV * CC / 4);
    cvt_split4<<<(unsigned)(((size_t)OQ  * CC / 4 + 255) / 256), 256>>>(W_q, Wqh, Wql, (size_t)OQ * CC / 4);
    cvt_split4<<<(unsigned)(((size_t)OP  * DH / 4 + 255) / 256), 256>>>(W_p, Wph, Wpl, (size_t)OP * DH / 4);

    // 1) kv = x @ W_kv^T ; prep (raw split + fused stats) ; BN finalize
    gemm_mma<0><<<dim3(OKV / 128, MKV / 128), 256, GEMM_SMEM>>>(xh, xl, Wkvh, Wkvl, Ykv, MKV, OKV, CC);
    prep_kv<<<dim3(14, HH, BB), 256>>>(Ykv, KH, KL, VTH, VTL, ps, pq);
    bn_finalize<<<OKV / 256, 256>>>(ps, pq, gkv, bkv, sckv, shkv, OKV, BB * 14, 1.f / MKV);

    // 2) q = xq @ W_q^T (gathered rows)
    gemm_mma<1><<<dim3(OQ / 128, MQ / 128), 256, GEMM_SMEM>>>(xh, xl, Wqh, Wql, Yq, MQ, OQ, CC);
    col_partial<<<dim3(OQ / 256, 64), 256>>>(Yq, ps, pq, MQ, OQ);
    bn_finalize<<<OQ / 256, 256>>>(ps, pq, gq, bq, scq, shq, OQ, 64, 1.f / MQ);

    // 3) attention + hard-swish (raw K/V; BN folded into Q and epilogue)
    attn_mma2<<<dim3(4, HH, BB), 256, ATTN_SMEM>>>(
        KH, KL, VTH, VTL, Yq, scq, shq, sckv, shkv, ab, bidx, Yoh, Yol);

    // 4) proj
    gemm_mma<0><<<dim3(OP / 128, MQ / 128), 256, GEMM_SMEM>>>(Yoh, Yol, Wph, Wpl, Yp, MQ, OP, DH);
    col_partial<<<dim3(OP / 256, 64), 256>>>(Yp, ps, pq, MQ, OP);
    bn_finalize<<<OP / 256, 256>>>(ps, pq, gp, bp, scp, shp, OP, 64, 1.f / MQ);
    bn_apply4<<<(MQ * OP / 4) / 256, 256>>>(
        reinterpret_cast<const float4*>(Yp), scp, shp,
        reinterpret_cast<float4*>(out), OP / 4);
}

// round 14
// speedup vs baseline: 1.1385x; 1.1385x over previous
#include <cuda_runtime.h>
#include <cuda_bf16.h>
#include <cstdint>

// ---------------------------------------------------------------- constants
#define EPSV      1e-5f
#define SCALE_QK  0.17677669529663687f   // 1/sqrt(32)

#define BB   64
#define NN   784
#define NQ   196
#define CC   512
#define HH   16
#define OKV  1536
#define OQ   512
#define DH   1024
#define OP   768
#define MKV  (BB*NN)  // 50176
#define MQ   (BB*NQ)  // 12544

// ---------------------------------------------------------------- scratch
__device__ float g_Ykv[(size_t)MKV * OKV];
__device__ float g_Yq [(size_t)MQ  * OQ];
__device__ float g_Yp [(size_t)MQ  * OP];
__device__ float g_ps [(size_t)(BB * 14) * OKV];
__device__ float g_pq [(size_t)(BB * 14) * OKV];
__device__ float g_ps2[64 * OKV];        // reduce14 output (disjoint!)
__device__ float g_pq2[64 * OKV];
__device__ float g_sc_kv[OKV], g_sh_kv[OKV];
__device__ float g_sc_q [OQ],  g_sh_q [OQ];
__device__ float g_sc_p [OP],  g_sh_p [OP];

// bf16 split operands
__device__ __nv_bfloat16 g_xh [(size_t)MKV * CC],  g_xl [(size_t)MKV * CC];
__device__ __nv_bfloat16 g_Wkvh[(size_t)OKV * CC], g_Wkvl[(size_t)OKV * CC];
__device__ __nv_bfloat16 g_Wqh [(size_t)OQ  * CC], g_Wql [(size_t)OQ  * CC];
__device__ __nv_bfloat16 g_Wph [(size_t)OP  * DH], g_Wpl [(size_t)OP  * DH];
__device__ __nv_bfloat16 g_Yoh [(size_t)MQ  * DH], g_Yol [(size_t)MQ  * DH];

// prepped attention operands (RAW values, bf16 split; V transposed)
__device__ __nv_bfloat16 g_KH [(size_t)BB * HH * NN * 32], g_KL [(size_t)BB * HH * NN * 32];
__device__ __nv_bfloat16 g_VTH[(size_t)BB * HH * 64 * NN], g_VTL[(size_t)BB * HH * 64 * NN];

// ---------------------------------------------------------------- helpers
__device__ __forceinline__ uint32_t smem_u32(const void* p) {
    uint32_t a;
    asm("{ .reg .u64 t; cvta.to.shared.u64 t, %1; cvt.u32.u64 %0, t; }" : "=r"(a) : "l"(p));
    return a;
}
__device__ __forceinline__ void cp_async16(uint32_t dst, const void* src) {
    asm volatile("cp.async.cg.shared.global [%0], [%1], 16;" :: "r"(dst), "l"(src) : "memory");
}
__device__ __forceinline__ void cp_commit() {
    asm volatile("cp.async.commit_group;" ::: "memory");
}
template<int N>
__device__ __forceinline__ void cp_wait() {
    asm volatile("cp.async.wait_group %0;" :: "n"(N) : "memory");
}
__device__ __forceinline__ void mma16816(float* c, uint32_t a0, uint32_t a1,
                                         uint32_t a2, uint32_t a3,
                                         uint32_t b0, uint32_t b1) {
    asm volatile(
        "mma.sync.aligned.m16n8k16.row.col.f32.bf16.bf16.f32 "
        "{%0,%1,%2,%3}, {%4,%5,%6,%7}, {%8,%9}, {%0,%1,%2,%3};"
        : "+f"(c[0]), "+f"(c[1]), "+f"(c[2]), "+f"(c[3])
        : "r"(a0), "r"(a1), "r"(a2), "r"(a3), "r"(b0), "r"(b1));
}
__device__ __forceinline__ void ldsm_x4(uint32_t addr, uint32_t& r0, uint32_t& r1,
                                        uint32_t& r2, uint32_t& r3) {
    asm volatile("ldmatrix.sync.aligned.m8n8.x4.shared.b16 {%0,%1,%2,%3}, [%4];"
        : "=r"(r0), "=r"(r1), "=r"(r2), "=r"(r3) : "r"(addr));
}
__device__ __forceinline__ void ldsm_x2(uint32_t addr, uint32_t& r0, uint32_t& r1) {
    asm volatile("ldmatrix.sync.aligned.m8n8.x2.shared.b16 {%0,%1}, [%2];"
        : "=r"(r0), "=r"(r1) : "r"(addr));
}

// ---------------------------------------------------------------- fp32 -> bf16 hi/lo split
__global__ void __launch_bounds__(256) cvt_split4(
    const float* __restrict__ X, __nv_bfloat16* __restrict__ H,
    __nv_bfloat16* __restrict__ L, size_t n4)
{
    size_t i = (size_t)blockIdx.x * 256 + threadIdx.x;
    if (i >= n4) return;
    float4 v = reinterpret_cast<const float4*>(X)[i];
    __nv_bfloat16 hx = __float2bfloat16(v.x);
    __nv_bfloat16 hy = __float2bfloat16(v.y);
    __nv_bfloat16 hz = __float2bfloat16(v.z);
    __nv_bfloat16 hw = __float2bfloat16(v.w);
    __nv_bfloat16 lx = __float2bfloat16(v.x - __bfloat162float(hx));
    __nv_bfloat16 ly = __float2bfloat16(v.y - __bfloat162float(hy));
    __nv_bfloat16 lz = __float2bfloat16(v.z - __bfloat162float(hz));
    __nv_bfloat16 lw = __float2bfloat16(v.w - __bfloat162float(hw));
    reinterpret_cast<__nv_bfloat162*>(H)[2 * i]     = __halves2bfloat162(hx, hy);
    reinterpret_cast<__nv_bfloat162*>(H)[2 * i + 1] = __halves2bfloat162(hz, hw);
    reinterpret_cast<__nv_bfloat162*>(L)[2 * i]     = __halves2bfloat162(lx, ly);
    reinterpret_cast<__nv_bfloat162*>(L)[2 * i + 1] = __halves2bfloat162(lz, lw);
}

// ---------------------------------------------------------------- mma.sync bf16-split GEMM (round-11 proven)
#define LDA_B    80
#define MAT_B    (128 * LDA_B)
#define STAGE_B  (4 * MAT_B)
#define GEMM_SMEM (2 * STAGE_B)

template<int GATHER>
__device__ __forceinline__ void load_chunk(
    const __nv_bfloat16* __restrict__ Ah_g, const __nv_bfloat16* __restrict__ Al_g,
    const __nv_bfloat16* __restrict__ Bh_g, const __nv_bfloat16* __restrict__ Bl_g,
    uint32_t sbase, int mBase, int nBase, int k0, int K, int tid)
{
    #pragma unroll
    for (int i = 0; i < 8; i++) {
        int u = tid + i * 256;
        int mat = u >> 9;
        int r   = (u >> 2) & 127;
        int seg = u & 3;
        const __nv_bfloat16* src;
        int row;
        if (mat < 2) {
            row = mBase + r;
            if (GATHER) {
                int bb = row / 196;
                int t  = row - bb * 196;
                row = bb * 784 + (t / 14) * 56 + (t % 14) * 2;
            }
            src = (mat == 0) ? Ah_g : Al_g;
        } else {
            row = nBase + r;
            src = (mat == 2) ? Bh_g : Bl_g;
        }
        cp_async16(sbase + mat * MAT_B + r * LDA_B + seg * 16,
                   src + (size_t)row * K + k0 + seg * 8);
    }
}

__device__ __forceinline__ void compute_chunk(
    uint32_t stage, float acc[2][8][4], int wm, int wn, int lane)
{
    const int sub    = lane >> 3;
    const int arow_f = (lane & 7) + ((sub & 1) << 3);
    const int akof   = (sub >> 1) << 3;
    const int brow_f = lane & 7;
    const int bkof   = ((lane >> 3) & 1) << 3;

    #pragma unroll
    for (int ks = 0; ks < 2; ks++) {
        const int kb = ks * 16;
        uint32_t Ahf[2][4], Alf[2][4];
        #pragma unroll
        for (int mt = 0; mt < 2; mt++) {
            uint32_t aaddr = stage + (uint32_t)(wm + mt * 16 + arow_f) * LDA_B
                           + (uint32_t)(kb + akof) * 2;
            ldsm_x4(aaddr,         Ahf[mt][0], Ahf[mt][1], Ahf[mt][2], Ahf[mt][3]);
            ldsm_x4(aaddr + MAT_B, Alf[mt][0], Alf[mt][1], Alf[mt][2], Alf[mt][3]);
        }
        #pragma unroll
        for (int nt = 0; nt < 8; nt++) {
            uint32_t baddr = stage + 2 * MAT_B + (uint32_t)(wn + nt * 8 + brow_f) * LDA_B
                           + (uint32_t)(kb + bkof) * 2;
            uint32_t bh0, bh1, bl0, bl1;
            ldsm_x2(baddr,         bh0, bh1);
            ldsm_x2(baddr + MAT_B, bl0, bl1);
            #pragma unroll
            for (int mt = 0; mt < 2; mt++) {
                mma16816(acc[mt][nt], Ahf[mt][0], Ahf[mt][1], Ahf[mt][2], Ahf[mt][3], bh0, bh1);
                mma16816(acc[mt][nt], Ahf[mt][0], Ahf[mt][1], Ahf[mt][2], Ahf[mt][3], bl0, bl1);
                mma16816(acc[mt][nt], Alf[mt][0], Alf[mt][1], Alf[mt][2], Alf[mt][3], bh0, bh1);
            }
        }
    }
}

template<int GATHER>
__global__ void __launch_bounds__(256) gemm_mma(
    const __nv_bfloat16* __restrict__ Ah_g, const __nv_bfloat16* __restrict__ Al_g,
    const __nv_bfloat16* __restrict__ Bh_g, const __nv_bfloat16* __restrict__ Bl_g,
    float* __restrict__ C, int M, int N, int K)
{
    extern __shared__ char gsm[];
    const int tid = threadIdx.x;
    const int wid = tid >> 5, lane = tid & 31;
    const int mBase = blockIdx.y * 128;
    const int nBase = blockIdx.x * 128;
    const int wm = (wid & 3) * 32;
    const int wn = (wid >> 2) * 64;

    const uint32_t sbase = smem_u32(gsm);

    float acc[2][8][4];
    #pragma unroll
    for (int mt = 0; mt < 2; mt++)
        #pragma unroll
        for (int nt = 0; nt < 8; nt++)
            #pragma unroll
            for (int j = 0; j < 4; j++) acc[mt][nt][j] = 0.f;

    const int nc = K >> 5;

    load_chunk<GATHER>(Ah_g, Al_g, Bh_g, Bl_g, sbase, mBase, nBase, 0, K, tid);
    cp_commit();

    for (int c = 0; c < nc; c++) {
        if (c + 1 < nc) {
            load_chunk<GATHER>(Ah_g, Al_g, Bh_g, Bl_g,
                               sbase + ((c + 1) & 1) * STAGE_B,
                               mBase, nBase, (c + 1) * 32, K, tid);
            cp_commit();
            cp_wait<1>();
        } else {
            cp_wait<0>();
        }
        __syncthreads();
        compute_chunk(sbase + (c & 1) * STAGE_B, acc, wm, wn, lane);
        __syncthreads();
    }

    const uint32_t g  = lane >> 2;
    const uint32_t t4 = lane & 3;
    #pragma unroll
    for (int mt = 0; mt < 2; mt++) {
        #pragma unroll
        for (int nt = 0; nt < 8; nt++) {
            const int col = nBase + wn + nt * 8 + t4 * 2;
            const int r0 = mBase + wm + mt * 16 + g;
            float2 v0 = make_float2(acc[mt][nt][0], acc[mt][nt][1]);
            float2 v1 = make_float2(acc[mt][nt][2], acc[mt][nt][3]);
            *reinterpret_cast<float2*>(C + (size_t)r0 * N + col)       = v0;
            *reinterpret_cast<float2*>(C + (size_t)(r0 + 8) * N + col) = v1;
        }
    }
}

// ---------------------------------------------------------------- column reduce (partial, 64 chunks)
__global__ void __launch_bounds__(256) col_partial(
    const float* __restrict__ Y, float* __restrict__ ps, float* __restrict__ pq,
    int M, int Ncols)
{
    const int col = blockIdx.x * 256 + threadIdx.x;
    const int ch  = blockIdx.y;
    const int per = (M + 63) >> 6;
    const int r0 = ch * per;
    int r1 = r0 + per; if (r1 > M) r1 = M;
    float s = 0.f, s2 = 0.f;
    for (int r = r0; r < r1; r++) {
        float v = Y[(size_t)r * Ncols + col];
        s += v;
        s2 = fmaf(v, v, s2);
    }
    ps[(size_t)ch * Ncols + col] = s;
    pq[(size_t)ch * Ncols + col] = s2;
}

// ---------------------------------------------------------------- reduce 14 chunk-partials -> 1 (DISJOINT output)
__global__ void __launch_bounds__(256) reduce14(
    const float* __restrict__ ps, const float* __restrict__ pq,
    float* __restrict__ ps2, float* __restrict__ pq2, int Ncols)
{
    const int col = blockIdx.x * 256 + threadIdx.x;
    const int by  = blockIdx.y;
    float s = 0.f, q = 0.f;
    #pragma unroll
    for (int c = 0; c < 14; c++) {
        s += ps[(size_t)(by * 14 + c) * Ncols + col];
        q += pq[(size_t)(by * 14 + c) * Ncols + col];
    }
    ps2[(size_t)by * Ncols + col] = s;
    pq2[(size_t)by * Ncols + col] = q;
}

// ---------------------------------------------------------------- BN finalize (nch chunks)
__global__ void __launch_bounds__(256) bn_finalize(
    const float* __restrict__ ps, const float* __restrict__ pq,
    const float* __restrict__ g, const float* __restrict__ b,
    float* __restrict__ scale, float* __restrict__ shift,
    int Ncols, int nch, float invM)
{
    const int col = blockIdx.x * 256 + threadIdx.x;
    float s = 0.f, s2 = 0.f;
    for (int c = 0; c < nch; c++) {
        s  += ps[(size_t)c * Ncols + col];
        s2 += pq[(size_t)c * Ncols + col];
    }
    float m   = s * invM;
    float var = s2 * invM - m * m;
    float sc  = g[col] * rsqrtf(var + EPSV);
    scale[col] = sc;
    shift[col] = b[col] - m * sc;
}

// ---------------------------------------------------------------- K/V prep (raw split + transpose) + fused column stats
__global__ void __launch_bounds__(256) prep_kv(
    const float* __restrict__ Ykv,
    __nv_bfloat16* __restrict__ KH, __nv_bfloat16* __restrict__ KL,
    __nv_bfloat16* __restrict__ VTH, __nv_bfloat16* __restrict__ VTL,
    float* __restrict__ ps, float* __restrict__ pq)
{
    __shared__ __align__(16) __nv_bfloat16 sVh[64 * 56];
    __shared__ __align__(16) __nv_bfloat16 sVl[64 * 56];
    __shared__ float pS[10][96], pQ[10][96];

    const int tid = threadIdx.x;
    const int kc = blockIdx.x, h = blockIdx.y, b = blockIdx.z;
    const int kb = kc * 56;
    const int bh = b * HH + h;

    const int f = tid % 24;
    const int rg = tid / 24;

    if (rg < 10) {
        float s4[4] = {0.f, 0.f, 0.f, 0.f};
        float q4[4] = {0.f, 0.f, 0.f, 0.f};
        for (int r = rg; r < 56; r += 10) {
            float4 v = *(reinterpret_cast<const float4*>(
                Ykv + (size_t)(b * NN + kb + r) * OKV + h * 96) + f);
            float vv[4] = {v.x, v.y, v.z, v.w};
            #pragma unroll
            for (int j = 0; j < 4; j++) {
                s4[j] += vv[j];
                q4[j] = fmaf(vv[j], vv[j], q4[j]);
            }
            if (f < 8) {
                int d = f * 4;
                __nv_bfloat16 hh[4], ll[4];
                #pragma unroll
                for (int j = 0; j < 4; j++) {
                    hh[j] = __float2bfloat16(vv[j]);
                    ll[j] = __float2bfloat16(vv[j] - __bfloat162float(hh[j]));
                }
                size_t base = ((size_t)bh * NN + kb + r) * 32 + d;
                reinterpret_cast<__nv_bfloat162*>(KH + base)[0] = __halves2bfloat162(hh[0], hh[1]);
                reinterpret_cast<__nv_bfloat162*>(KH + base)[1] = __halves2bfloat162(hh[2], hh[3]);
                reinterpret_cast<__nv_bfloat162*>(KL + base)[0] = __halves2bfloat162(ll[0], ll[1]);
                reinterpret_cast<__nv_bfloat162*>(KL + base)[1] = __halves2bfloat162(ll[2], ll[3]);
            } else {
                int d = (f - 8) * 4;
                #pragma unroll
                for (int j = 0; j < 4; j++) {
                    __nv_bfloat16 hh = __float2bfloat16(vv[j]);
                    sVh[(d + j) * 56 + r] = hh;
                    sVl[(d + j) * 56 + r] = __float2bfloat16(vv[j] - __bfloat162float(hh));
                }
            }
        }
        #pragma unroll
        for (int j = 0; j < 4; j++) { pS[rg][f * 4 + j] = s4[j]; pQ[rg][f * 4 + j] = q4[j]; }
    }
    __syncthreads();

    if (tid < 96) {
        float s = 0.f, q = 0.f;
        #pragma unroll
        for (int gi = 0; gi < 10; gi++) { s += pS[gi][tid]; q += pQ[gi][tid]; }
        size_t chunk = (size_t)(b * 14 + kc);
        ps[chunk * OKV + h * 96 + tid] = s;
        pq[chunk * OKV + h * 96 + tid] = q;
    }

    for (int u = tid; u < 64 * 7; u += 256) {
        int d = u / 7, seg = u - d * 7;
        uint4 vh = *reinterpret_cast<const uint4*>(&sVh[d * 56 + seg * 8]);
        uint4 vl = *reinterpret_cast<const uint4*>(&sVl[d * 56 + seg * 8]);
        size_t base = ((size_t)bh * 64 + d) * NN + kb + seg * 8;
        *reinterpret_cast<uint4*>(VTH + base) = vh;
        *reinterpret_cast<uint4*>(VTL + base) = vl;
    }
}

// ---------------------------------------------------------------- attention (tensor-core, raw K/V, folded BN)
__device__ __forceinline__ float hswish(float x) {
    float t = fminf(fmaxf(x + 3.f, 0.f), 6.f);
    return x * t * (1.f / 6.f);
}

// smem byte offsets
#define AQP 80
#define AVP 144
#define K_ST 4480
#define V_ST 9216
#define O_QH 0
#define O_QL 5120
#define O_KH 10240
#define O_KL 19200
#define O_VH 28160
#define O_VL 46592
#define O_PH 65024
#define O_PL 74240
#define O_S  83456
#define O_BH 94432
#define O_SCQ 97568
#define O_SHQ 97696
#define O_SCK 97824
#define O_SCV 97952
#define O_SHV 98208
#define O_MR 98464
#define O_LR 98720
#define O_AR 98976
#define ATTN_SMEM 99232

__global__ void __launch_bounds__(256) attn_mma2(
    const __nv_bfloat16* __restrict__ KHg, const __nv_bfloat16* __restrict__ KLg,
    const __nv_bfloat16* __restrict__ VTHg, const __nv_bfloat16* __restrict__ VTLg,
    const float* __restrict__ Yq,
    const float* __restrict__ scq,  const float* __restrict__ shq,
    const float* __restrict__ sckv, const float* __restrict__ shkv,
    const float* __restrict__ biases, const int* __restrict__ bidx,
    __nv_bfloat16* __restrict__ Yoh, __nv_bfloat16* __restrict__ Yol)
{
    extern __shared__ char sm[];
    __nv_bfloat16* Qh = reinterpret_cast<__nv_bfloat16*>(sm + O_QH);
    __nv_bfloat16* Ql = reinterpret_cast<__nv_bfloat16*>(sm + O_QL);
    __nv_bfloat16* Ph = reinterpret_cast<__nv_bfloat16*>(sm + O_PH);
    __nv_bfloat16* Pl = reinterpret_cast<__nv_bfloat16*>(sm + O_PL);
    float* S    = reinterpret_cast<float*>(sm + O_S);
    float* bh   = reinterpret_cast<float*>(sm + O_BH);
    float* scqh = reinterpret_cast<float*>(sm + O_SCQ);
    float* shqh = reinterpret_cast<float*>(sm + O_SHQ);
    float* sckh = reinterpret_cast<float*>(sm + O_SCK);
    float* scvh = reinterpret_cast<float*>(sm + O_SCV);
    float* shvh = reinterpret_cast<float*>(sm + O_SHV);
    float* mrow = reinterpret_cast<float*>(sm + O_MR);
    float* lrow = reinterpret_cast<float*>(sm + O_LR);
    float* arow = reinterpret_cast<float*>(sm + O_AR);

    const int tid = threadIdx.x;
    const int wid = tid >> 5, lane = tid & 31;
    const int qg = blockIdx.x, h = blockIdx.y, b = blockIdx.z;
    const int bh_idx = b * HH + h;

    const __nv_bfloat16* KHb = KHg + (size_t)bh_idx * NN * 32;
    const __nv_bfloat16* KLb = KLg + (size_t)bh_idx * NN * 32;
    const __nv_bfloat16* VHb = VTHg + (size_t)bh_idx * 64 * NN;
    const __nv_bfloat16* VLb = VTLg + (size_t)bh_idx * 64 * NN;

    const uint32_t sbase = smem_u32(sm);
    const uint32_t uQH = sbase + O_QH, uQL = sbase + O_QL;
    const uint32_t uKH = sbase + O_KH, uKL = sbase + O_KL;
    const uint32_t uVH = sbase + O_VH, uVL = sbase + O_VL;
    const uint32_t uPH = sbase + O_PH, uPL = sbase + O_PL;

    if (tid < 32) {
        scqh[tid] = scq[h * 32 + tid];
        shqh[tid] = shq[h * 32 + tid];
        sckh[tid] = sckv[h * 96 + tid];
    } else if (tid < 96) {
        int d = tid - 32;
        scvh[d] = sckv[h * 96 + 32 + d];
        shvh[d] = shkv[h * 96 + 32 + d];
    }
    for (int i = tid; i < 784; i += 256) bh[i] = biases[h * 784 + i];
    if (tid < 64) { mrow[tid] = -1e30f; lrow[tid] = 0.f; arow[tid] = 0.f; }
    for (int u = tid; u < 150; u += 256) {
        int m = u / 75, w = u - m * 75;
        int r = 49 + w / 5, sgm = w - (w / 5) * 5;
        uint32_t off = (m == 0 ? O_QH : O_QL) + (uint32_t)r * AQP + sgm * 16;
        *reinterpret_cast<uint4*>(sm + off) = make_uint4(0, 0, 0, 0);
    }
    for (int u = tid; u < 512; u += 256) {
        int m = u >> 8, w = u & 255;
        int st = w >> 7, w2 = w & 127;
        int d = w2 >> 1, half = w2 & 1;
        uint32_t off = (m == 0 ? O_VH : O_VL) + st * V_ST + (uint32_t)d * AVP + 112 + half * 16;
        *reinterpret_cast<uint4*>(sm + off) = make_uint4(0, 0, 0, 0);
    }
    for (int u = tid; u < 1152; u += 256)
        reinterpret_cast<uint4*>(sm + O_PH)[u] = make_uint4(0, 0, 0, 0);
    __syncthreads();

    for (int e = tid; e < 49 * 32; e += 256) {
        int r = e >> 5, d = e & 31;
        float v = fmaf(Yq[(size_t)(b * NQ + qg * 49 + r) * OQ + h * 32 + d], scqh[d], shqh[d]) * sckh[d];
        __nv_bfloat16 hh = __float2bfloat16(v);
        Qh[r * 40 + d] = hh;
        Ql[r * 40 + d] = __float2bfloat16(v - __bfloat162float(hh));
    }

    auto issue_chunk = [&](int kc) {
        const int st = kc & 1;
        const int kb = kc * 56;
        #pragma unroll
        for (int i = 0; i < 6; i++) {
            int u = tid + i * 256;
            if (u >= 1344) break;
            if (u < 448) {
                int hi = (u < 224);
                int w = hi ? u : u - 224;
                int r = w >> 2, seg = w & 3;
                const __nv_bfloat16* src = (hi ? KHb : KLb) + (size_t)(kb + r) * 32 + seg * 8;
                uint32_t dst = (hi ? uKH : uKL) + st * K_ST + (uint32_t)r * AQP + seg * 16;
                cp_async16(dst, src);
            } else {
                int v = u - 448;
                int hi = (v < 448);
                int w = hi ? v : v - 448;
                int d = w / 7, seg = w - d * 7;
                const __nv_bfloat16* src = (hi ? VHb : VLb) + (size_t)d * NN + kb + seg * 8;
                uint32_t dst = (hi ? uVH : uVL) + st * V_ST + (uint32_t)d * AVP + seg * 16;
                cp_async16(dst, src);
            }
        }
        cp_commit();
    };

    const int mw  = wid >> 1;
    const int nt0 = (wid & 1) * 4;
    const int ntn = (wid & 1) ? 3 : 4;
    const int g   = lane >> 2, t4 = lane & 3;
    const int sub = lane >> 3;
    const int arow_f = (lane & 7) + ((sub & 1) << 3);
    const int akof   = (sub >> 1) << 3;
    const int brow_f = lane & 7;
    const int bkof   = ((lane >> 3) & 1) << 3;
    const int sr = (tid < 196) ? (tid >> 2) : 48;
    const int sq = tid & 3;
    const bool sact = (tid < 196);

    float accp[4][4];
    #pragma unroll
    for (int i = 0; i < 4; i++)
        #pragma unroll
        for (int j = 0; j < 4; j++) accp[i][j] = 0.f;

    issue_chunk(0);

    for (int kc = 0; kc < 14; kc++) {
        const int st = kc & 1;
        const int kb = kc * 56;

        cp_wait<0>();
        __syncthreads();

        if (kc + 1 < 14) issue_chunk(kc + 1);

        // ---- QK mma + bias + write S
        {
            float acc[4][4];
            #pragma unroll
            for (int i = 0; i < 4; i++)
                #pragma unroll
                for (int j = 0; j < 4; j++) acc[i][j] = 0.f;
            #pragma unroll
            for (int ks = 0; ks < 2; ks++) {
                uint32_t aoff = (uint32_t)(mw * 16 + arow_f) * AQP + (uint32_t)(ks * 16 + akof) * 2;
                uint32_t Ahf[4], Alf[4];
                ldsm_x4(uQH + aoff, Ahf[0], Ahf[1], Ahf[2], Ahf[3]);
                ldsm_x4(uQL + aoff, Alf[0], Alf[1], Alf[2], Alf[3]);
                for (int nti = 0; nti < ntn; nti++) {
                    int nt = nt0 + nti;
                    uint32_t boff = st * K_ST + (uint32_t)(nt * 8 + brow_f) * AQP
                                  + (uint32_t)(ks * 16 + bkof) * 2;
                    uint32_t bh0, bh1, bl0, bl1;
                    ldsm_x2(uKH + boff, bh0, bh1);
                    ldsm_x2(uKL + boff, bl0, bl1);
                    mma16816(acc[nti], Ahf[0], Ahf[1], Ahf[2], Ahf[3], bh0, bh1);
                    mma16816(acc[nti], Ahf[0], Ahf[1], Ahf[2], Ahf[3], bl0, bl1);
                    mma16816(acc[nti], Alf[0], Alf[1], Alf[2], Alf[3], bh0, bh1);
                }
            }
            const int r0 = mw * 16 + g;
            for (int nti = 0; nti < ntn; nti++) {
                int nt = nt0 + nti;
                int c0 = nt * 8 + t4 * 2;
                if (r0 < 49) {
                    int2 id = *reinterpret_cast<const int2*>(
                        &bidx[(size_t)(qg * 49 + r0) * NN + kb + c0]);
                    float2 s0 = make_float2(fmaf(acc[nti][0], SCALE_QK, bh[id.x]),
                                            fmaf(acc[nti][1], SCALE_QK, bh[id.y]));
                    *reinterpret_cast<float2*>(&S[r0 * 56 + c0]) = s0;
                }
                if (r0 + 8 < 49) {
                    int2 id = *reinterpret_cast<const int2*>(
                        &bidx[(size_t)(qg * 49 + r0 + 8) * NN + kb + c0]);
                    float2 s1 = make_float2(fmaf(acc[nti][2], SCALE_QK, bh[id.x]),
                                            fmaf(acc[nti][3], SCALE_QK, bh[id.y]));
                    *reinterpret_cast<float2*>(&S[(r0 + 8) * 56 + c0]) = s1;
                }
            }
        }
        __syncthreads();

        // ---- online softmax, write P bf16 hi/lo
        {
            float xv[14];
            float cm = -1e30f;
            #pragma unroll
            for (int j = 0; j < 14; j++) {
                xv[j] = S[sr * 56 + sq + 4 * j];
                cm = fmaxf(cm, xv[j]);
            }
            cm = fmaxf(cm, __shfl_xor_sync(0xffffffffu, cm, 1));
            cm = fmaxf(cm, __shfl_xor_sync(0xffffffffu, cm, 2));
            float mo = mrow[sr];
            float mn = fmaxf(mo, cm);
            float cs = 0.f;
            #pragma unroll
            for (int j = 0; j < 14; j++) {
                float p = __expf(xv[j] - mn);
                xv[j] = p;
                cs += p;
            }
            cs += __shfl_xor_sync(0xffffffffu, cs, 1);
            cs += __shfl_xor_sync(0xffffffffu, cs, 2);
            if (sact) {
                #pragma unroll
                for (int j = 0; j < 14; j++) {
                    __nv_bfloat16 ph = __float2bfloat16(xv[j]);
                    Ph[sr * 72 + sq + 4 * j] = ph;
                    Pl[sr * 72 + sq + 4 * j] = __float2bfloat16(xv[j] - __bfloat162float(ph));
                }
                if (sq == 0) {
                    float a = __expf(mo - mn);
                    arow[sr] = a;
                    lrow[sr] = lrow[sr] * a + cs;
                    mrow[sr] = mn;
                }
            }
        }
        __syncthreads();

        // ---- PV mma with rescale
        {
            const int r0 = mw * 16 + g;
            float a0 = arow[r0], a1 = arow[r0 + 8];
            #pragma unroll
            for (int nti = 0; nti < 4; nti++) {
                accp[nti][0] *= a0; accp[nti][1] *= a0;
                accp[nti][2] *= a1; accp[nti][3] *= a1;
            }
            #pragma unroll
            for (int ks = 0; ks < 4; ks++) {
                uint32_t aoff = (uint32_t)(mw * 16 + arow_f) * AVP + (uint32_t)(ks * 16 + akof) * 2;
                uint32_t Phf[4], Plf[4];
                ldsm_x4(uPH + aoff, Phf[0], Phf[1], Phf[2], Phf[3]);
                ldsm_x4(uPL + aoff, Plf[0], Plf[1], Plf[2], Plf[3]);
                #pragma unroll
                for (int nti = 0; nti < 4; nti++) {
                    int dt8 = ((wid & 1) * 4 + nti) * 8;
                    uint32_t boff = st * V_ST + (uint32_t)(dt8 + brow_f) * AVP
                                  + (uint32_t)(ks * 16 + bkof) * 2;
                    uint32_t vh0, vh1, vl0, vl1;
                    ldsm_x2(uVH + boff, vh0, vh1);
                    ldsm_x2(uVL + boff, vl0, vl1);
                    mma16816(accp[nti], Phf[0], Phf[1], Phf[2], Phf[3], vh0, vh1);
                    mma16816(accp[nti], Phf[0], Phf[1], Phf[2], Phf[3], vl0, vl1);
                    mma16816(accp[nti], Plf[0], Plf[1], Plf[2], Plf[3], vh0, vh1);
                }
            }
        }
    }

    // ---- epilogue: out = hswish(scv * acc/l + shv), bf16 hi/lo store
    const int r0 = mw * 16 + g;
    #pragma unroll
    for (int half = 0; half < 2; half++) {
        int rr = r0 + half * 8;
        if (rr >= 49) continue;
        float inv = 1.0f / lrow[rr];
        int q = qg * 49 + rr;
        #pragma unroll
        for (int nti = 0; nti < 4; nti++) {
            int c0 = (wid & 1) * 32 + nti * 8 + t4 * 2;
            float o0 = hswish(fmaf(accp[nti][half * 2 + 0] * inv, scvh[c0],     shvh[c0]));
            float o1 = hswish(fmaf(accp[nti][half * 2 + 1] * inv, scvh[c0 + 1], shvh[c0 + 1]));
            __nv_bfloat16 h0 = __float2bfloat16(o0);
            __nv_bfloat16 h1 = __float2bfloat16(o1);
            __nv_bfloat16 l0 = __float2bfloat16(o0 - __bfloat162float(h0));
            __nv_bfloat16 l1 = __float2bfloat16(o1 - __bfloat162float(h1));
            size_t base = (size_t)(b * NQ + q) * DH + h * 64 + c0;
            *reinterpret_cast<__nv_bfloat162*>(Yoh + base) = __halves2bfloat162(h0, h1);
            *reinterpret_cast<__nv_bfloat162*>(Yol + base) = __halves2bfloat162(l0, l1);
        }
    }
}

// ---------------------------------------------------------------- final BN apply (float4)
__global__ void __launch_bounds__(256) bn_apply4(
    const float4* __restrict__ Y, const float* __restrict__ scale,
    const float* __restrict__ shift, float4* __restrict__ out, int Ncols4)
{
    const int i = blockIdx.x * 256 + threadIdx.x;
    float4 v = Y[i];
    const int c = (i % Ncols4) * 4;
    out[i] = make_float4(fmaf(v.x, scale[c + 0], shift[c + 0]),
                         fmaf(v.y, scale[c + 1], shift[c + 1]),
                         fmaf(v.z, scale[c + 2], shift[c + 2]),
                         fmaf(v.w, scale[c + 3], shift[c + 3]));
}

// ---------------------------------------------------------------- launch
extern "C" void kernel_launch(void* const* d_in, const int* in_sizes, int n_in,
                              void* d_out, int out_size)
{
    const float* x    = (const float*)d_in[0];
    const float* W_kv = (const float*)d_in[1];
    const float* gkv  = (const float*)d_in[2];
    const float* bkv  = (const float*)d_in[3];
    const float* W_q  = (const float*)d_in[4];
    const float* gq   = (const float*)d_in[5];
    const float* bq   = (const float*)d_in[6];
    const float* W_p  = (const float*)d_in[7];
    const float* gp   = (const float*)d_in[8];
    const float* bp   = (const float*)d_in[9];
    const float* ab   = (const float*)d_in[10];
    const int*   bidx = (const int*)d_in[11];
    float* out = (float*)d_out;

    float *Ykv, *Yq, *Yp, *ps, *pq, *ps2, *pq2;
    float *sckv, *shkv, *scq, *shq, *scp, *shp;
    __nv_bfloat16 *xh, *xl, *Wkvh, *Wkvl, *Wqh, *Wql, *Wph, *Wpl, *Yoh, *Yol;
    __nv_bfloat16 *KH, *KL, *VTH, *VTL;
    cudaGetSymbolAddress((void**)&Ykv, g_Ykv);
    cudaGetSymbolAddress((void**)&Yq,  g_Yq);
    cudaGetSymbolAddress((void**)&Yp,  g_Yp);
    cudaGetSymbolAddress((void**)&ps,  g_ps);
    cudaGetSymbolAddress((void**)&pq,  g_pq);
    cudaGetSymbolAddress((void**)&ps2, g_ps2);
    cudaGetSymbolAddress((void**)&pq2, g_pq2);
    cudaGetSymbolAddress((void**)&sckv, g_sc_kv);
    cudaGetSymbolAddress((void**)&shkv, g_sh_kv);
    cudaGetSymbolAddress((void**)&scq,  g_sc_q);
    cudaGetSymbolAddress((void**)&shq,  g_sh_q);
    cudaGetSymbolAddress((void**)&scp,  g_sc_p);
    cudaGetSymbolAddress((void**)&shp,  g_sh_p);
    cudaGetSymbolAddress((void**)&xh,   g_xh);
    cudaGetSymbolAddress((void**)&xl,   g_xl);
    cudaGetSymbolAddress((void**)&Wkvh, g_Wkvh);
    cudaGetSymbolAddress((void**)&Wkvl, g_Wkvl);
    cudaGetSymbolAddress((void**)&Wqh,  g_Wqh);
    cudaGetSymbolAddress((void**)&Wql,  g_Wql);
    cudaGetSymbolAddress((void**)&Wph,  g_Wph);
    cudaGetSymbolAddress((void**)&Wpl,  g_Wpl);
    cudaGetSymbolAddress((void**)&Yoh,  g_Yoh);
    cudaGetSymbolAddress((void**)&Yol,  g_Yol);
    cudaGetSymbolAddress((void**)&KH,   g_KH);
    cudaGetSymbolAddress((void**)&KL,   g_KL);
    cudaGetSymbolAddress((void**)&VTH,  g_VTH);
    cudaGetSymbolAddress((void**)&VTL,  g_VTL);

    cudaFuncSetAttribute(gemm_mma<0>, cudaFuncAttributeMaxDynamicSharedMemorySize, GEMM_SMEM);
    cudaFuncSetAttribute(gemm_mma<1>, cudaFuncAttributeMaxDynamicSharedMemorySize, GEMM_SMEM);
    cudaFuncSetAttribute(attn_mma2, cudaFuncAttributeMaxDynamicSharedMemorySize, ATTN_SMEM);

    // 0) bf16 hi/lo splits
    cvt_split4<<<(unsigned)(((size_t)MKV * CC / 4 + 255) / 256), 256>>>(x, xh, xl, (size_t)MKV * CC / 4);
    cvt_split4<<<(unsigned)(((size_t)OKV * CC / 4 + 255) / 256), 256>>>(W_kv, Wkvh, Wkvl, (size_t)OKV * CC / 4);
    cvt_split4<<<(unsigned)(((size_t)OQ  * CC / 4 + 255) / 256), 256>>>(W_q, Wqh, Wql, (size_t)OQ * CC / 4);
    cvt_split4<<<(unsigned)(((size_t)OP  * DH / 4 + 255) / 256), 256>>>(W_p, Wph, Wpl, (size_t)OP * DH / 4);

    // 1) kv GEMM ; prep (raw split + fused stats) ; reduce (disjoint out) ; BN finalize
    gemm_mma<0><<<dim3(OKV / 128, MKV / 128), 256, GEMM_SMEM>>>(xh, xl, Wkvh, Wkvl, Ykv, MKV, OKV, CC);
    prep_kv<<<dim3(14, HH, BB), 256>>>(Ykv, KH, KL, VTH, VTL, ps, pq);
    reduce14<<<dim3(OKV / 256, 64), 256>>>(ps, pq, ps2, pq2, OKV);
    bn_finalize<<<OKV / 256, 256>>>(ps2, pq2, gkv, bkv, sckv, shkv, OKV, 64, 1.f / MKV);

    // 2) q = xq @ W_q^T (gathered rows)
    gemm_mma<1><<<dim3(OQ / 128, MQ / 128), 256, GEMM_SMEM>>>(xh, xl, Wqh, Wql, Yq, MQ, OQ, CC);
    col_partial<<<dim3(OQ / 256, 64), 256>>>(Yq, ps, pq, MQ, OQ);
    bn_finalize<<<OQ / 256, 256>>>(ps, pq, gq, bq, scq, shq, OQ, 64, 1.f / MQ);

    // 3) attention + hard-swish (raw K/V; BN folded into Q and epilogue)
    attn_mma2<<<dim3(4, HH, BB), 256, ATTN_SMEM>>>(
        KH, KL, VTH, VTL, Yq, scq, shq, sckv, shkv, ab, bidx, Yoh, Yol);

    // 4) proj
    gemm_mma<0><<<dim3(OP / 128, MQ / 128), 256, GEMM_SMEM>>>(Yoh, Yol, Wph, Wpl, Yp, MQ, OP, DH);
    col_partial<<<dim3(OP / 256, 64), 256>>>(Yp, ps, pq, MQ, OP);
    bn_finalize<<<OP / 256, 256>>>(ps, pq, gp, bp, scp, shp, OP, 64, 1.f / MQ);
    bn_apply4<<<(MQ * OP / 4) / 256, 256>>>(
        reinterpret_cast<const float4*>(Yp), scp, shp,
        reinterpret_cast<float4*>(out), OP / 4);
}

// round 15
// speedup vs baseline: 1.2352x; 1.0849x over previous
#include <cuda_runtime.h>
#include <cuda_fp16.h>
#include <cstdint>

// ---------------------------------------------------------------- constants
#define EPSV      1e-5f
#define SCALE_QK  0.17677669529663687f   // 1/sqrt(32)

#define BB   64
#define NN   784
#define NQ   196
#define CC   512
#define HH   16
#define OKV  1536
#define OQ   512
#define DH   1024
#define OP   768
#define MKV  (BB*NN)  // 50176
#define MQ   (BB*NQ)  // 12544

// ---------------------------------------------------------------- scratch
__device__ float g_Ykv[(size_t)MKV * OKV];
__device__ float g_Yq [(size_t)MQ  * OQ];
__device__ float g_Yp [(size_t)MQ  * OP];
__device__ float g_ps [(size_t)(BB * 14) * OKV];
__device__ float g_pq [(size_t)(BB * 14) * OKV];
__device__ float g_ps2[64 * OKV];
__device__ float g_pq2[64 * OKV];
__device__ float g_sc_kv[OKV], g_sh_kv[OKV];
__device__ float g_sc_q [OQ],  g_sh_q [OQ];
__device__ float g_sc_p [OP],  g_sh_p [OP];

// fp16 split operands
__device__ __half g_xh [(size_t)MKV * CC],  g_xl [(size_t)MKV * CC];
__device__ __half g_Wkvh[(size_t)OKV * CC], g_Wkvl[(size_t)OKV * CC];
__device__ __half g_Wqh [(size_t)OQ  * CC], g_Wql [(size_t)OQ  * CC];
__device__ __half g_Wph [(size_t)OP  * DH], g_Wpl [(size_t)OP  * DH];
__device__ __half g_Yoh [(size_t)MQ  * DH], g_Yol [(size_t)MQ  * DH];

// prepped attention operands (RAW values, fp16 split; V transposed)
__device__ __half g_KH [(size_t)BB * HH * NN * 32], g_KL [(size_t)BB * HH * NN * 32];
__device__ __half g_VTH[(size_t)BB * HH * 64 * NN], g_VTL[(size_t)BB * HH * 64 * NN];

// ---------------------------------------------------------------- helpers
__device__ __forceinline__ uint32_t smem_u32(const void* p) {
    uint32_t a;
    asm("{ .reg .u64 t; cvta.to.shared.u64 t, %1; cvt.u32.u64 %0, t; }" : "=r"(a) : "l"(p));
    return a;
}
__device__ __forceinline__ void cp_async16(uint32_t dst, const void* src) {
    asm volatile("cp.async.cg.shared.global [%0], [%1], 16;" :: "r"(dst), "l"(src) : "memory");
}
__device__ __forceinline__ void cp_commit() {
    asm volatile("cp.async.commit_group;" ::: "memory");
}
template<int N>
__device__ __forceinline__ void cp_wait() {
    asm volatile("cp.async.wait_group %0;" :: "n"(N) : "memory");
}
__device__ __forceinline__ void mma16816(float* c, uint32_t a0, uint32_t a1,
                                         uint32_t a2, uint32_t a3,
                                         uint32_t b0, uint32_t b1) {
    asm volatile(
        "mma.sync.aligned.m16n8k16.row.col.f32.f16.f16.f32 "
        "{%0,%1,%2,%3}, {%4,%5,%6,%7}, {%8,%9}, {%0,%1,%2,%3};"
        : "+f"(c[0]), "+f"(c[1]), "+f"(c[2]), "+f"(c[3])
        : "r"(a0), "r"(a1), "r"(a2), "r"(a3), "r"(b0), "r"(b1));
}
__device__ __forceinline__ void ldsm_x4(uint32_t addr, uint32_t& r0, uint32_t& r1,
                                        uint32_t& r2, uint32_t& r3) {
    asm volatile("ldmatrix.sync.aligned.m8n8.x4.shared.b16 {%0,%1,%2,%3}, [%4];"
        : "=r"(r0), "=r"(r1), "=r"(r2), "=r"(r3) : "r"(addr));
}
__device__ __forceinline__ void ldsm_x2(uint32_t addr, uint32_t& r0, uint32_t& r1) {
    asm volatile("ldmatrix.sync.aligned.m8n8.x2.shared.b16 {%0,%1}, [%2];"
        : "=r"(r0), "=r"(r1) : "r"(addr));
}

// ---------------------------------------------------------------- fp32 -> fp16 hi/lo split
__global__ void __launch_bounds__(256) cvt_split4(
    const float* __restrict__ X, __half* __restrict__ H,
    __half* __restrict__ L, size_t n4)
{
    size_t i = (size_t)blockIdx.x * 256 + threadIdx.x;
    if (i >= n4) return;
    float4 v = reinterpret_cast<const float4*>(X)[i];
    __half hx = __float2half(v.x);
    __half hy = __float2half(v.y);
    __half hz = __float2half(v.z);
    __half hw = __float2half(v.w);
    __half lx = __float2half(v.x - __half2float(hx));
    __half ly = __float2half(v.y - __half2float(hy));
    __half lz = __float2half(v.z - __half2float(hz));
    __half lw = __float2half(v.w - __half2float(hw));
    reinterpret_cast<__half2*>(H)[2 * i]     = __halves2half2(hx, hy);
    reinterpret_cast<__half2*>(H)[2 * i + 1] = __halves2half2(hz, hw);
    reinterpret_cast<__half2*>(L)[2 * i]     = __halves2half2(lx, ly);
    reinterpret_cast<__half2*>(L)[2 * i + 1] = __halves2half2(lz, lw);
}

// ---------------------------------------------------------------- mma.sync fp16-split GEMM
// PASSES=3: AhBh + AhBl + AlBh (err ~2^-22). PASSES=2: AhBh + AlBh = A*fp16(B).
#define LDA_B    80
#define MAT_B    (128 * LDA_B)
#define STAGE_B  (4 * MAT_B)
#define GEMM_SMEM (2 * STAGE_B)

template<int GATHER, int PASSES>
__device__ __forceinline__ void load_chunk(
    const __half* __restrict__ Ah_g, const __half* __restrict__ Al_g,
    const __half* __restrict__ Bh_g, const __half* __restrict__ Bl_g,
    uint32_t sbase, int mBase, int nBase, int k0, int K, int tid)
{
    const int NSEG = (PASSES == 3) ? 2048 : 1536;   // 4 or 3 matrices
    #pragma unroll
    for (int i = 0; i < 8; i++) {
        int u = tid + i * 256;
        if (u >= NSEG) break;
        int mat = u >> 9;
        int r   = (u >> 2) & 127;
        int seg = u & 3;
        const __half* src;
        int row;
        if (mat < 2) {
            row = mBase + r;
            if (GATHER) {
                int bb = row / 196;
                int t  = row - bb * 196;
                row = bb * 784 + (t / 14) * 56 + (t % 14) * 2;
            }
            src = (mat == 0) ? Ah_g : Al_g;
        } else {
            row = nBase + r;
            src = (mat == 2) ? Bh_g : Bl_g;
        }
        cp_async16(sbase + mat * MAT_B + r * LDA_B + seg * 16,
                   src + (size_t)row * K + k0 + seg * 8);
    }
}

template<int PASSES>
__device__ __forceinline__ void compute_chunk(
    uint32_t stage, float acc[2][8][4], int wm, int wn, int lane)
{
    const int sub    = lane >> 3;
    const int arow_f = (lane & 7) + ((sub & 1) << 3);
    const int akof   = (sub >> 1) << 3;
    const int brow_f = lane & 7;
    const int bkof   = ((lane >> 3) & 1) << 3;

    #pragma unroll
    for (int ks = 0; ks < 2; ks++) {
        const int kb = ks * 16;
        uint32_t Ahf[2][4], Alf[2][4];
        #pragma unroll
        for (int mt = 0; mt < 2; mt++) {
            uint32_t aaddr = stage + (uint32_t)(wm + mt * 16 + arow_f) * LDA_B
                           + (uint32_t)(kb + akof) * 2;
            ldsm_x4(aaddr,         Ahf[mt][0], Ahf[mt][1], Ahf[mt][2], Ahf[mt][3]);
            ldsm_x4(aaddr + MAT_B, Alf[mt][0], Alf[mt][1], Alf[mt][2], Alf[mt][3]);
        }
        #pragma unroll
        for (int nt = 0; nt < 8; nt++) {
            uint32_t baddr = stage + 2 * MAT_B + (uint32_t)(wn + nt * 8 + brow_f) * LDA_B
                           + (uint32_t)(kb + bkof) * 2;
            uint32_t bh0, bh1;
            ldsm_x2(baddr, bh0, bh1);
            if (PASSES == 3) {
                uint32_t bl0, bl1;
                ldsm_x2(baddr + MAT_B, bl0, bl1);
                #pragma unroll
                for (int mt = 0; mt < 2; mt++) {
                    mma16816(acc[mt][nt], Ahf[mt][0], Ahf[mt][1], Ahf[mt][2], Ahf[mt][3], bh0, bh1);
                    mma16816(acc[mt][nt], Ahf[mt][0], Ahf[mt][1], Ahf[mt][2], Ahf[mt][3], bl0, bl1);
                    mma16816(acc[mt][nt], Alf[mt][0], Alf[mt][1], Alf[mt][2], Alf[mt][3], bh0, bh1);
                }
            } else {
                #pragma unroll
                for (int mt = 0; mt < 2; mt++) {
                    mma16816(acc[mt][nt], Ahf[mt][0], Ahf[mt][1], Ahf[mt][2], Ahf[mt][3], bh0, bh1);
                    mma16816(acc[mt][nt], Alf[mt][0], Alf[mt][1], Alf[mt][2], Alf[mt][3], bh0, bh1);
                }
            }
        }
    }
}

template<int GATHER, int PASSES>
__global__ void __launch_bounds__(256) gemm_mma(
    const __half* __restrict__ Ah_g, const __half* __restrict__ Al_g,
    const __half* __restrict__ Bh_g, const __half* __restrict__ Bl_g,
    float* __restrict__ C, int M, int N, int K)
{
    extern __shared__ char gsm[];
    const int tid = threadIdx.x;
    const int wid = tid >> 5, lane = tid & 31;
    const int mBase = blockIdx.y * 128;
    const int nBase = blockIdx.x * 128;
    const int wm = (wid & 3) * 32;
    const int wn = (wid >> 2) * 64;

    const uint32_t sbase = smem_u32(gsm);

    float acc[2][8][4];
    #pragma unroll
    for (int mt = 0; mt < 2; mt++)
        #pragma unroll
        for (int nt = 0; nt < 8; nt++)
            #pragma unroll
            for (int j = 0; j < 4; j++) acc[mt][nt][j] = 0.f;

    const int nc = K >> 5;

    load_chunk<GATHER, PASSES>(Ah_g, Al_g, Bh_g, Bl_g, sbase, mBase, nBase, 0, K, tid);
    cp_commit();

    for (int c = 0; c < nc; c++) {
        if (c + 1 < nc) {
            load_chunk<GATHER, PASSES>(Ah_g, Al_g, Bh_g, Bl_g,
                               sbase + ((c + 1) & 1) * STAGE_B,
                               mBase, nBase, (c + 1) * 32, K, tid);
            cp_commit();
            cp_wait<1>();
        } else {
            cp_wait<0>();
        }
        __syncthreads();
        compute_chunk<PASSES>(sbase + (c & 1) * STAGE_B, acc, wm, wn, lane);
        __syncthreads();
    }

    const uint32_t g  = lane >> 2;
    const uint32_t t4 = lane & 3;
    #pragma unroll
    for (int mt = 0; mt < 2; mt++) {
        #pragma unroll
        for (int nt = 0; nt < 8; nt++) {
            const int col = nBase + wn + nt * 8 + t4 * 2;
            const int r0 = mBase + wm + mt * 16 + g;
            float2 v0 = make_float2(acc[mt][nt][0], acc[mt][nt][1]);
            float2 v1 = make_float2(acc[mt][nt][2], acc[mt][nt][3]);
            *reinterpret_cast<float2*>(C + (size_t)r0 * N + col)       = v0;
            *reinterpret_cast<float2*>(C + (size_t)(r0 + 8) * N + col) = v1;
        }
    }
}

// ---------------------------------------------------------------- column reduce (partial, 64 chunks)
__global__ void __launch_bounds__(256) col_partial(
    const float* __restrict__ Y, float* __restrict__ ps, float* __restrict__ pq,
    int M, int Ncols)
{
    const int col = blockIdx.x * 256 + threadIdx.x;
    const int ch  = blockIdx.y;
    const int per = (M + 63) >> 6;
    const int r0 = ch * per;
    int r1 = r0 + per; if (r1 > M) r1 = M;
    float s = 0.f, s2 = 0.f;
    for (int r = r0; r < r1; r++) {
        float v = Y[(size_t)r * Ncols + col];
        s += v;
        s2 = fmaf(v, v, s2);
    }
    ps[(size_t)ch * Ncols + col] = s;
    pq[(size_t)ch * Ncols + col] = s2;
}

// ---------------------------------------------------------------- reduce 14 chunk-partials -> 1 (DISJOINT output)
__global__ void __launch_bounds__(256) reduce14(
    const float* __restrict__ ps, const float* __restrict__ pq,
    float* __restrict__ ps2, float* __restrict__ pq2, int Ncols)
{
    const int col = blockIdx.x * 256 + threadIdx.x;
    const int by  = blockIdx.y;
    float s = 0.f, q = 0.f;
    #pragma unroll
    for (int c = 0; c < 14; c++) {
        s += ps[(size_t)(by * 14 + c) * Ncols + col];
        q += pq[(size_t)(by * 14 + c) * Ncols + col];
    }
    ps2[(size_t)by * Ncols + col] = s;
    pq2[(size_t)by * Ncols + col] = q;
}

// ---------------------------------------------------------------- BN finalize (nch chunks)
__global__ void __launch_bounds__(256) bn_finalize(
    const float* __restrict__ ps, const float* __restrict__ pq,
    const float* __restrict__ g, const float* __restrict__ b,
    float* __restrict__ scale, float* __restrict__ shift,
    int Ncols, int nch, float invM)
{
    const int col = blockIdx.x * 256 + threadIdx.x;
    float s = 0.f, s2 = 0.f;
    for (int c = 0; c < nch; c++) {
        s  += ps[(size_t)c * Ncols + col];
        s2 += pq[(size_t)c * Ncols + col];
    }
    float m   = s * invM;
    float var = s2 * invM - m * m;
    float sc  = g[col] * rsqrtf(var + EPSV);
    scale[col] = sc;
    shift[col] = b[col] - m * sc;
}

// ---------------------------------------------------------------- K/V prep (raw fp16 split + transpose) + fused column stats
__global__ void __launch_bounds__(256) prep_kv(
    const float* __restrict__ Ykv,
    __half* __restrict__ KH, __half* __restrict__ KL,
    __half* __restrict__ VTH, __half* __restrict__ VTL,
    float* __restrict__ ps, float* __restrict__ pq)
{
    __shared__ __align__(16) __half sVh[64 * 56];
    __shared__ __align__(16) __half sVl[64 * 56];
    __shared__ float pS[10][96], pQ[10][96];

    const int tid = threadIdx.x;
    const int kc = blockIdx.x, h = blockIdx.y, b = blockIdx.z;
    const int kb = kc * 56;
    const int bh = b * HH + h;

    const int f = tid % 24;
    const int rg = tid / 24;

    if (rg < 10) {
        float s4[4] = {0.f, 0.f, 0.f, 0.f};
        float q4[4] = {0.f, 0.f, 0.f, 0.f};
        for (int r = rg; r < 56; r += 10) {
            float4 v = *(reinterpret_cast<const float4*>(
                Ykv + (size_t)(b * NN + kb + r) * OKV + h * 96) + f);
            float vv[4] = {v.x, v.y, v.z, v.w};
            #pragma unroll
            for (int j = 0; j < 4; j++) {
                s4[j] += vv[j];
                q4[j] = fmaf(vv[j], vv[j], q4[j]);
            }
            if (f < 8) {
                int d = f * 4;
                __half hh[4], ll[4];
                #pragma unroll
                for (int j = 0; j < 4; j++) {
                    hh[j] = __float2half(vv[j]);
                    ll[j] = __float2half(vv[j] - __half2float(hh[j]));
                }
                size_t base = ((size_t)bh * NN + kb + r) * 32 + d;
                reinterpret_cast<__half2*>(KH + base)[0] = __halves2half2(hh[0], hh[1]);
                reinterpret_cast<__half2*>(KH + base)[1] = __halves2half2(hh[2], hh[3]);
                reinterpret_cast<__half2*>(KL + base)[0] = __halves2half2(ll[0], ll[1]);
                reinterpret_cast<__half2*>(KL + base)[1] = __halves2half2(ll[2], ll[3]);
            } else {
                int d = (f - 8) * 4;
                #pragma unroll
                for (int j = 0; j < 4; j++) {
                    __half hh = __float2half(vv[j]);
                    sVh[(d + j) * 56 + r] = hh;
                    sVl[(d + j) * 56 + r] = __float2half(vv[j] - __half2float(hh));
                }
            }
        }
        #pragma unroll
        for (int j = 0; j < 4; j++) { pS[rg][f * 4 + j] = s4[j]; pQ[rg][f * 4 + j] = q4[j]; }
    }
    __syncthreads();

    if (tid < 96) {
        float s = 0.f, q = 0.f;
        #pragma unroll
        for (int gi = 0; gi < 10; gi++) { s += pS[gi][tid]; q += pQ[gi][tid]; }
        size_t chunk = (size_t)(b * 14 + kc);
        ps[chunk * OKV + h * 96 + tid] = s;
        pq[chunk * OKV + h * 96 + tid] = q;
    }

    for (int u = tid; u < 64 * 7; u += 256) {
        int d = u / 7, seg = u - d * 7;
        uint4 vh = *reinterpret_cast<const uint4*>(&sVh[d * 56 + seg * 8]);
        uint4 vl = *reinterpret_cast<const uint4*>(&sVl[d * 56 + seg * 8]);
        size_t base = ((size_t)bh * 64 + d) * NN + kb + seg * 8;
        *reinterpret_cast<uint4*>(VTH + base) = vh;
        *reinterpret_cast<uint4*>(VTL + base) = vl;
    }
}

// ---------------------------------------------------------------- attention (tensor-core, raw K/V, folded BN)
__device__ __forceinline__ float hswish(float x) {
    float t = fminf(fmaxf(x + 3.f, 0.f), 6.f);
    return x * t * (1.f / 6.f);
}

// smem byte offsets
#define AQP 80
#define AVP 144
#define K_ST 4480
#define V_ST 9216
#define O_QH 0
#define O_QL 5120
#define O_KH 10240
#define O_KL 19200
#define O_VH 28160
#define O_VL 46592
#define O_PH 65024
#define O_PL 74240
#define O_S  83456
#define O_BH 94432
#define O_SCQ 97568
#define O_SHQ 97696
#define O_SCK 97824
#define O_SCV 97952
#define O_SHV 98208
#define O_MR 98464
#define O_LR 98720
#define O_AR 98976
#define ATTN_SMEM 99232

__global__ void __launch_bounds__(256) attn_mma2(
    const __half* __restrict__ KHg, const __half* __restrict__ KLg,
    const __half* __restrict__ VTHg, const __half* __restrict__ VTLg,
    const float* __restrict__ Yq,
    const float* __restrict__ scq,  const float* __restrict__ shq,
    const float* __restrict__ sckv, const float* __restrict__ shkv,
    const float* __restrict__ biases, const int* __restrict__ bidx,
    __half* __restrict__ Yoh, __half* __restrict__ Yol)
{
    extern __shared__ char sm[];
    __half* Qh = reinterpret_cast<__half*>(sm + O_QH);
    __half* Ql = reinterpret_cast<__half*>(sm + O_QL);
    __half* Ph = reinterpret_cast<__half*>(sm + O_PH);
    __half* Pl = reinterpret_cast<__half*>(sm + O_PL);
    float* S    = reinterpret_cast<float*>(sm + O_S);
    float* bh   = reinterpret_cast<float*>(sm + O_BH);
    float* scqh = reinterpret_cast<float*>(sm + O_SCQ);
    float* shqh = reinterpret_cast<float*>(sm + O_SHQ);
    float* sckh = reinterpret_cast<float*>(sm + O_SCK);
    float* scvh = reinterpret_cast<float*>(sm + O_SCV);
    float* shvh = reinterpret_cast<float*>(sm + O_SHV);
    float* mrow = reinterpret_cast<float*>(sm + O_MR);
    float* lrow = reinterpret_cast<float*>(sm + O_LR);
    float* arow = reinterpret_cast<float*>(sm + O_AR);

    const int tid = threadIdx.x;
    const int wid = tid >> 5, lane = tid & 31;
    const int qg = blockIdx.x, h = blockIdx.y, b = blockIdx.z;
    const int bh_idx = b * HH + h;

    const __half* KHb = KHg + (size_t)bh_idx * NN * 32;
    const __half* KLb = KLg + (size_t)bh_idx * NN * 32;
    const __half* VHb = VTHg + (size_t)bh_idx * 64 * NN;
    const __half* VLb = VTLg + (size_t)bh_idx * 64 * NN;

    const uint32_t sbase = smem_u32(sm);
    const uint32_t uQH = sbase + O_QH, uQL = sbase + O_QL;
    const uint32_t uKH = sbase + O_KH, uKL = sbase + O_KL;
    const uint32_t uVH = sbase + O_VH, uVL = sbase + O_VL;
    const uint32_t uPH = sbase + O_PH, uPL = sbase + O_PL;

    if (tid < 32) {
        scqh[tid] = scq[h * 32 + tid];
        shqh[tid] = shq[h * 32 + tid];
        sckh[tid] = sckv[h * 96 + tid];
    } else if (tid < 96) {
        int d = tid - 32;
        scvh[d] = sckv[h * 96 + 32 + d];
        shvh[d] = shkv[h * 96 + 32 + d];
    }
    for (int i = tid; i < 784; i += 256) bh[i] = biases[h * 784 + i];
    if (tid < 64) { mrow[tid] = -1e30f; lrow[tid] = 0.f; arow[tid] = 0.f; }
    for (int u = tid; u < 150; u += 256) {
        int m = u / 75, w = u - m * 75;
        int r = 49 + w / 5, sgm = w - (w / 5) * 5;
        uint32_t off = (m == 0 ? O_QH : O_QL) + (uint32_t)r * AQP + sgm * 16;
        *reinterpret_cast<uint4*>(sm + off) = make_uint4(0, 0, 0, 0);
    }
    for (int u = tid; u < 512; u += 256) {
        int m = u >> 8, w = u & 255;
        int st = w >> 7, w2 = w & 127;
        int d = w2 >> 1, half = w2 & 1;
        uint32_t off = (m == 0 ? O_VH : O_VL) + st * V_ST + (uint32_t)d * AVP + 112 + half * 16;
        *reinterpret_cast<uint4*>(sm + off) = make_uint4(0, 0, 0, 0);
    }
    for (int u = tid; u < 1152; u += 256)
        reinterpret_cast<uint4*>(sm + O_PH)[u] = make_uint4(0, 0, 0, 0);
    __syncthreads();

    for (int e = tid; e < 49 * 32; e += 256) {
        int r = e >> 5, d = e & 31;
        float v = fmaf(Yq[(size_t)(b * NQ + qg * 49 + r) * OQ + h * 32 + d], scqh[d], shqh[d]) * sckh[d];
        __half hh = __float2half(v);
        Qh[r * 40 + d] = hh;
        Ql[r * 40 + d] = __float2half(v - __half2float(hh));
    }

    auto issue_chunk = [&](int kc) {
        const int st = kc & 1;
        const int kb = kc * 56;
        #pragma unroll
        for (int i = 0; i < 6; i++) {
            int u = tid + i * 256;
            if (u >= 1344) break;
            if (u < 448) {
                int hi = (u < 224);
                int w = hi ? u : u - 224;
                int r = w >> 2, seg = w & 3;
                const __half* src = (hi ? KHb : KLb) + (size_t)(kb + r) * 32 + seg * 8;
                uint32_t dst = (hi ? uKH : uKL) + st * K_ST + (uint32_t)r * AQP + seg * 16;
                cp_async16(dst, src);
            } else {
                int v = u - 448;
                int hi = (v < 448);
                int w = hi ? v : v - 448;
                int d = w / 7, seg = w - d * 7;
                const __half* src = (hi ? VHb : VLb) + (size_t)d * NN + kb + seg * 8;
                uint32_t dst = (hi ? uVH : uVL) + st * V_ST + (uint32_t)d * AVP + seg * 16;
                cp_async16(dst, src);
            }
        }
        cp_commit();
    };

    const int mw  = wid >> 1;
    const int nt0 = (wid & 1) * 4;
    const int ntn = (wid & 1) ? 3 : 4;
    const int g   = lane >> 2, t4 = lane & 3;
    const int sub = lane >> 3;
    const int arow_f = (lane & 7) + ((sub & 1) << 3);
    const int akof   = (sub >> 1) << 3;
    const int brow_f = lane & 7;
    const int bkof   = ((lane >> 3) & 1) << 3;
    const int sr = (tid < 196) ? (tid >> 2) : 48;
    const int sq = tid & 3;
    const bool sact = (tid < 196);

    float accp[4][4];
    #pragma unroll
    for (int i = 0; i < 4; i++)
        #pragma unroll
        for (int j = 0; j < 4; j++) accp[i][j] = 0.f;

    issue_chunk(0);

    for (int kc = 0; kc < 14; kc++) {
        const int st = kc & 1;
        const int kb = kc * 56;

        cp_wait<0>();
        __syncthreads();

        if (kc + 1 < 14) issue_chunk(kc + 1);

        // ---- QK mma + bias + write S
        {
            float acc[4][4];
            #pragma unroll
            for (int i = 0; i < 4; i++)
                #pragma unroll
                for (int j = 0; j < 4; j++) acc[i][j] = 0.f;
            #pragma unroll
            for (int ks = 0; ks < 2; ks++) {
                uint32_t aoff = (uint32_t)(mw * 16 + arow_f) * AQP + (uint32_t)(ks * 16 + akof) * 2;
                uint32_t Ahf[4], Alf[4];
                ldsm_x4(uQH + aoff, Ahf[0], Ahf[1], Ahf[2], Ahf[3]);
                ldsm_x4(uQL + aoff, Alf[0], Alf[1], Alf[2], Alf[3]);
                for (int nti = 0; nti < ntn; nti++) {
                    int nt = nt0 + nti;
                    uint32_t boff = st * K_ST + (uint32_t)(nt * 8 + brow_f) * AQP
                                  + (uint32_t)(ks * 16 + bkof) * 2;
                    uint32_t bh0, bh1, bl0, bl1;
                    ldsm_x2(uKH + boff, bh0, bh1);
                    ldsm_x2(uKL + boff, bl0, bl1);
                    mma16816(acc[nti], Ahf[0], Ahf[1], Ahf[2], Ahf[3], bh0, bh1);
                    mma16816(acc[nti], Ahf[0], Ahf[1], Ahf[2], Ahf[3], bl0, bl1);
                    mma16816(acc[nti], Alf[0], Alf[1], Alf[2], Alf[3], bh0, bh1);
                }
            }
            const int r0 = mw * 16 + g;
            for (int nti = 0; nti < ntn; nti++) {
                int nt = nt0 + nti;
                int c0 = nt * 8 + t4 * 2;
                if (r0 < 49) {
                    int2 id = *reinterpret_cast<const int2*>(
                        &bidx[(size_t)(qg * 49 + r0) * NN + kb + c0]);
                    float2 s0 = make_float2(fmaf(acc[nti][0], SCALE_QK, bh[id.x]),
                                            fmaf(acc[nti][1], SCALE_QK, bh[id.y]));
                    *reinterpret_cast<float2*>(&S[r0 * 56 + c0]) = s0;
                }
                if (r0 + 8 < 49) {
                    int2 id = *reinterpret_cast<const int2*>(
                        &bidx[(size_t)(qg * 49 + r0 + 8) * NN + kb + c0]);
                    float2 s1 = make_float2(fmaf(acc[nti][2], SCALE_QK, bh[id.x]),
                                            fmaf(acc[nti][3], SCALE_QK, bh[id.y]));
                    *reinterpret_cast<float2*>(&S[(r0 + 8) * 56 + c0]) = s1;
                }
            }
        }
        __syncthreads();

        // ---- online softmax, write P fp16 hi/lo
        {
            float xv[14];
            float cm = -1e30f;
            #pragma unroll
            for (int j = 0; j < 14; j++) {
                xv[j] = S[sr * 56 + sq + 4 * j];
                cm = fmaxf(cm, xv[j]);
            }
            cm = fmaxf(cm, __shfl_xor_sync(0xffffffffu, cm, 1));
            cm = fmaxf(cm, __shfl_xor_sync(0xffffffffu, cm, 2));
            float mo = mrow[sr];
            float mn = fmaxf(mo, cm);
            float cs = 0.f;
            #pragma unroll
            for (int j = 0; j < 14; j++) {
                float p = __expf(xv[j] - mn);
                xv[j] = p;
                cs += p;
            }
            cs += __shfl_xor_sync(0xffffffffu, cs, 1);
            cs += __shfl_xor_sync(0xffffffffu, cs, 2);
            if (sact) {
                #pragma unroll
                for (int j = 0; j < 14; j++) {
                    __half ph = __float2half(xv[j]);
                    Ph[sr * 72 + sq + 4 * j] = ph;
                    Pl[sr * 72 + sq + 4 * j] = __float2half(xv[j] - __half2float(ph));
                }
                if (sq == 0) {
                    float a = __expf(mo - mn);
                    arow[sr] = a;
                    lrow[sr] = lrow[sr] * a + cs;
                    mrow[sr] = mn;
                }
            }
        }
        __syncthreads();

        // ---- PV mma with rescale
        {
            const int r0 = mw * 16 + g;
            float a0 = arow[r0], a1 = arow[r0 + 8];
            #pragma unroll
            for (int nti = 0; nti < 4; nti++) {
                accp[nti][0] *= a0; accp[nti][1] *= a0;
                accp[nti][2] *= a1; accp[nti][3] *= a1;
            }
            #pragma unroll
            for (int ks = 0; ks < 4; ks++) {
                uint32_t aoff = (uint32_t)(mw * 16 + arow_f) * AVP + (uint32_t)(ks * 16 + akof) * 2;
                uint32_t Phf[4], Plf[4];
                ldsm_x4(uPH + aoff, Phf[0], Phf[1], Phf[2], Phf[3]);
                ldsm_x4(uPL + aoff, Plf[0], Plf[1], Plf[2], Plf[3]);
                #pragma unroll
                for (int nti = 0; nti < 4; nti++) {
                    int dt8 = ((wid & 1) * 4 + nti) * 8;
                    uint32_t boff = st * V_ST + (uint32_t)(dt8 + brow_f) * AVP
                                  + (uint32_t)(ks * 16 + bkof) * 2;
                    uint32_t vh0, vh1, vl0, vl1;
                    ldsm_x2(uVH + boff, vh0, vh1);
                    ldsm_x2(uVL + boff, vl0, vl1);
                    mma16816(accp[nti], Phf[0], Phf[1], Phf[2], Phf[3], vh0, vh1);
                    mma16816(accp[nti], Phf[0], Phf[1], Phf[2], Phf[3], vl0, vl1);
                    mma16816(accp[nti], Plf[0], Plf[1], Plf[2], Plf[3], vh0, vh1);
                }
            }
        }
    }

    // ---- epilogue: out = hswish(scv * acc/l + shv), fp16 hi/lo store
    const int r0 = mw * 16 + g;
    #pragma unroll
    for (int half = 0; half < 2; half++) {
        int rr = r0 + half * 8;
        if (rr >= 49) continue;
        float inv = 1.0f / lrow[rr];
        int q = qg * 49 + rr;
        #pragma unroll
        for (int nti = 0; nti < 4; nti++) {
            int c0 = (wid & 1) * 32 + nti * 8 + t4 * 2;
            float o0 = hswish(fmaf(accp[nti][half * 2 + 0] * inv, scvh[c0],     shvh[c0]));
            float o1 = hswish(fmaf(accp[nti][half * 2 + 1] * inv, scvh[c0 + 1], shvh[c0 + 1]));
            __half h0 = __float2half(o0);
            __half h1 = __float2half(o1);
            __half l0 = __float2half(o0 - __half2float(h0));
            __half l1 = __float2half(o1 - __half2float(h1));
            size_t base = (size_t)(b * NQ + q) * DH + h * 64 + c0;
            *reinterpret_cast<__half2*>(Yoh + base) = __halves2half2(h0, h1);
            *reinterpret_cast<__half2*>(Yol + base) = __halves2half2(l0, l1);
        }
    }
}

// ---------------------------------------------------------------- final BN apply (float4)
__global__ void __launch_bounds__(256) bn_apply4(
    const float4* __restrict__ Y, const float* __restrict__ scale,
    const float* __restrict__ shift, float4* __restrict__ out, int Ncols4)
{
    const int i = blockIdx.x * 256 + threadIdx.x;
    float4 v = Y[i];
    const int c = (i % Ncols4) * 4;
    out[i] = make_float4(fmaf(v.x, scale[c + 0], shift[c + 0]),
                         fmaf(v.y, scale[c + 1], shift[c + 1]),
                         fmaf(v.z, scale[c + 2], shift[c + 2]),
                         fmaf(v.w, scale[c + 3], shift[c + 3]));
}

// ---------------------------------------------------------------- launch
extern "C" void kernel_launch(void* const* d_in, const int* in_sizes, int n_in,
                              void* d_out, int out_size)
{
    const float* x    = (const float*)d_in[0];
    const float* W_kv = (const float*)d_in[1];
    const float* gkv  = (const float*)d_in[2];
    const float* bkv  = (const float*)d_in[3];
    const float* W_q  = (const float*)d_in[4];
    const float* gq   = (const float*)d_in[5];
    const float* bq   = (const float*)d_in[6];
    const float* W_p  = (const float*)d_in[7];
    const float* gp   = (const float*)d_in[8];
    const float* bp   = (const float*)d_in[9];
    const float* ab   = (const float*)d_in[10];
    const int*   bidx = (const int*)d_in[11];
    float* out = (float*)d_out;

    float *Ykv, *Yq, *Yp, *ps, *pq, *ps2, *pq2;
    float *sckv, *shkv, *scq, *shq, *scp, *shp;
    __half *xh, *xl, *Wkvh, *Wkvl, *Wqh, *Wql, *Wph, *Wpl, *Yoh, *Yol;
    __half *KH, *KL, *VTH, *VTL;
    cudaGetSymbolAddress((void**)&Ykv, g_Ykv);
    cudaGetSymbolAddress((void**)&Yq,  g_Yq);
    cudaGetSymbolAddress((void**)&Yp,  g_Yp);
    cudaGetSymbolAddress((void**)&ps,  g_ps);
    cudaGetSymbolAddress((void**)&pq,  g_pq);
    cudaGetSymbolAddress((void**)&ps2, g_ps2);
    cudaGetSymbolAddress((void**)&pq2, g_pq2);
    cudaGetSymbolAddress((void**)&sckv, g_sc_kv);
    cudaGetSymbolAddress((void**)&shkv, g_sh_kv);
    cudaGetSymbolAddress((void**)&scq,  g_sc_q);
    cudaGetSymbolAddress((void**)&shq,  g_sh_q);
    cudaGetSymbolAddress((void**)&scp,  g_sc_p);
    cudaGetSymbolAddress((void**)&shp,  g_sh_p);
    cudaGetSymbolAddress((void**)&xh,   g_xh);
    cudaGetSymbolAddress((void**)&xl,   g_xl);
    cudaGetSymbolAddress((void**)&Wkvh, g_Wkvh);
    cudaGetSymbolAddress((void**)&Wkvl, g_Wkvl);
    cudaGetSymbolAddress((void**)&Wqh,  g_Wqh);
    cudaGetSymbolAddress((void**)&Wql,  g_Wql);
    cudaGetSymbolAddress((void**)&Wph,  g_Wph);
    cudaGetSymbolAddress((void**)&Wpl,  g_Wpl);
    cudaGetSymbolAddress((void**)&Yoh,  g_Yoh);
    cudaGetSymbolAddress((void**)&Yol,  g_Yol);
    cudaGetSymbolAddress((void**)&KH,   g_KH);
    cudaGetSymbolAddress((void**)&KL,   g_KL);
    cudaGetSymbolAddress((void**)&VTH,  g_VTH);
    cudaGetSymbolAddress((void**)&VTL,  g_VTL);

    cudaFuncSetAttribute((const void*)gemm_mma<0,2>, cudaFuncAttributeMaxDynamicSharedMemorySize, GEMM_SMEM);
    cudaFuncSetAttribute((const void*)gemm_mma<0,3>, cudaFuncAttributeMaxDynamicSharedMemorySize, GEMM_SMEM);
    cudaFuncSetAttribute((const void*)gemm_mma<1,3>, cudaFuncAttributeMaxDynamicSharedMemorySize, GEMM_SMEM);
    cudaFuncSetAttribute(attn_mma2, cudaFuncAttributeMaxDynamicSharedMemorySize, ATTN_SMEM);

    // 0) fp16 hi/lo splits
    cvt_split4<<<(unsigned)(((size_t)MKV * CC / 4 + 255) / 256), 256>>>(x, xh, xl, (size_t)MKV * CC / 4);
    cvt_split4<<<(unsigned)(((size_t)OKV * CC / 4 + 255) / 256), 256>>>(W_kv, Wkvh, Wkvl, (size_t)OKV * CC / 4);
    cvt_split4<<<(unsigned)(((size_t)OQ  * CC / 4 + 255) / 256), 256>>>(W_q, Wqh, Wql, (size_t)OQ * CC / 4);
    cvt_split4<<<(unsigned)(((size_t)OP  * DH / 4 + 255) / 256), 256>>>(W_p, Wph, Wpl, (size_t)OP * DH / 4);

    // 1) kv GEMM (2-pass fp16) ; prep ; reduce ; BN finalize
    gemm_mma<0,2><<<dim3(OKV / 128, MKV / 128), 256, GEMM_SMEM>>>(xh, xl, Wkvh, Wkvl, Ykv, MKV, OKV, CC);
    prep_kv<<<dim3(14, HH, BB), 256>>>(Ykv, KH, KL, VTH, VTL, ps, pq);
    reduce14<<<dim3(OKV / 256, 64), 256>>>(ps, pq, ps2, pq2, OKV);
    bn_finalize<<<OKV / 256, 256>>>(ps2, pq2, gkv, bkv, sckv, shkv, OKV, 64, 1.f / MKV);

    // 2) q = xq @ W_q^T (gathered rows, 3-pass fp16)
    gemm_mma<1,3><<<dim3(OQ / 128, MQ / 128), 256, GEMM_SMEM>>>(xh, xl, Wqh, Wql, Yq, MQ, OQ, CC);
    col_partial<<<dim3(OQ / 256, 64), 256>>>(Yq, ps, pq, MQ, OQ);
    bn_finalize<<<OQ / 256, 256>>>(ps, pq, gq, bq, scq, shq, OQ, 64, 1.f / MQ);

    // 3) attention + hard-swish
    attn_mma2<<<dim3(4, HH, BB), 256, ATTN_SMEM>>>(
        KH, KL, VTH, VTL, Yq, scq, shq, sckv, shkv, ab, bidx, Yoh, Yol);

    // 4) proj (3-pass fp16)
    gemm_mma<0,3><<<dim3(OP / 128, MQ / 128), 256, GEMM_SMEM>>>(Yoh, Yol, Wph, Wpl, Yp, MQ, OP, DH);
    col_partial<<<dim3(OP / 256, 64), 256>>>(Yp, ps, pq, MQ, OP);
    bn_finalize<<<OP / 256, 256>>>(ps, pq, gp, bp, scp, shp, OP, 64, 1.f / MQ);
    bn_apply4<<<(MQ * OP / 4) / 256, 256>>>(
        reinterpret_cast<const float4*>(Yp), scp, shp,
        reinterpret_cast<float4*>(out), OP / 4);
}

// round 16
// speedup vs baseline: 1.2731x; 1.0306x over previous
#include <cuda_runtime.h>
#include <cuda_fp16.h>
#include <cstdint>

// ---------------------------------------------------------------- constants
#define EPSV      1e-5f
#define SCALE_QK  0.17677669529663687f   // 1/sqrt(32)

#define BB   64
#define NN   784
#define NQ   196
#define CC   512
#define HH   16
#define OKV  1536
#define OQ   512
#define DH   1024
#define OP   768
#define MKV  (BB*NN)  // 50176
#define MQ   (BB*NQ)  // 12544

// ---------------------------------------------------------------- scratch
__device__ float g_Ykv[(size_t)MKV * OKV];
__device__ float g_Yq [(size_t)MQ  * OQ];
__device__ float g_Yp [(size_t)MQ  * OP];
__device__ float g_ps [(size_t)(BB * 14) * OKV];
__device__ float g_pq [(size_t)(BB * 14) * OKV];
__device__ float g_ps2[64 * OKV];
__device__ float g_pq2[64 * OKV];
__device__ float g_sc_kv[OKV], g_sh_kv[OKV];
__device__ float g_sc_q [OQ],  g_sh_q [OQ];
__device__ float g_sc_p [OP],  g_sh_p [OP];

// fp16 split operands
__device__ __half g_xh [(size_t)MKV * CC],  g_xl [(size_t)MKV * CC];
__device__ __half g_Wkvh[(size_t)OKV * CC], g_Wkvl[(size_t)OKV * CC];
__device__ __half g_Wqh [(size_t)OQ  * CC], g_Wql [(size_t)OQ  * CC];
__device__ __half g_Wph [(size_t)OP  * DH], g_Wpl [(size_t)OP  * DH];
__device__ __half g_Yoh [(size_t)MQ  * DH], g_Yol [(size_t)MQ  * DH];

// prepped attention operands (RAW values, fp16 split; V transposed)
__device__ __half g_KH [(size_t)BB * HH * NN * 32], g_KL [(size_t)BB * HH * NN * 32];
__device__ __half g_VTH[(size_t)BB * HH * 64 * NN], g_VTL[(size_t)BB * HH * 64 * NN];

// ---------------------------------------------------------------- helpers
__device__ __forceinline__ uint32_t smem_u32(const void* p) {
    uint32_t a;
    asm("{ .reg .u64 t; cvta.to.shared.u64 t, %1; cvt.u32.u64 %0, t; }" : "=r"(a) : "l"(p));
    return a;
}
__device__ __forceinline__ void cp_async16(uint32_t dst, const void* src) {
    asm volatile("cp.async.cg.shared.global [%0], [%1], 16;" :: "r"(dst), "l"(src) : "memory");
}
__device__ __forceinline__ void cp_commit() {
    asm volatile("cp.async.commit_group;" ::: "memory");
}
template<int N>
__device__ __forceinline__ void cp_wait() {
    asm volatile("cp.async.wait_group %0;" :: "n"(N) : "memory");
}
__device__ __forceinline__ void mma16816(float* c, uint32_t a0, uint32_t a1,
                                         uint32_t a2, uint32_t a3,
                                         uint32_t b0, uint32_t b1) {
    asm volatile(
        "mma.sync.aligned.m16n8k16.row.col.f32.f16.f16.f32 "
        "{%0,%1,%2,%3}, {%4,%5,%6,%7}, {%8,%9}, {%0,%1,%2,%3};"
        : "+f"(c[0]), "+f"(c[1]), "+f"(c[2]), "+f"(c[3])
        : "r"(a0), "r"(a1), "r"(a2), "r"(a3), "r"(b0), "r"(b1));
}
__device__ __forceinline__ void ldsm_x4(uint32_t addr, uint32_t& r0, uint32_t& r1,
                                        uint32_t& r2, uint32_t& r3) {
    asm volatile("ldmatrix.sync.aligned.m8n8.x4.shared.b16 {%0,%1,%2,%3}, [%4];"
        : "=r"(r0), "=r"(r1), "=r"(r2), "=r"(r3) : "r"(addr));
}
__device__ __forceinline__ void ldsm_x2(uint32_t addr, uint32_t& r0, uint32_t& r1) {
    asm volatile("ldmatrix.sync.aligned.m8n8.x2.shared.b16 {%0,%1}, [%2];"
        : "=r"(r0), "=r"(r1) : "r"(addr));
}

// ---------------------------------------------------------------- fp32 -> fp16 hi/lo split
__global__ void __launch_bounds__(256) cvt_split4(
    const float* __restrict__ X, __half* __restrict__ H,
    __half* __restrict__ L, size_t n4)
{
    size_t i = (size_t)blockIdx.x * 256 + threadIdx.x;
    if (i >= n4) return;
    float4 v = reinterpret_cast<const float4*>(X)[i];
    __half hx = __float2half(v.x);
    __half hy = __float2half(v.y);
    __half hz = __float2half(v.z);
    __half hw = __float2half(v.w);
    __half lx = __float2half(v.x - __half2float(hx));
    __half ly = __float2half(v.y - __half2float(hy));
    __half lz = __float2half(v.z - __half2float(hz));
    __half lw = __float2half(v.w - __half2float(hw));
    reinterpret_cast<__half2*>(H)[2 * i]     = __halves2half2(hx, hy);
    reinterpret_cast<__half2*>(H)[2 * i + 1] = __halves2half2(hz, hw);
    reinterpret_cast<__half2*>(L)[2 * i]     = __halves2half2(lx, ly);
    reinterpret_cast<__half2*>(L)[2 * i + 1] = __halves2half2(lz, lw);
}

// ---------------------------------------------------------------- mma.sync fp16-split GEMM
// PASSES=3: AhBh + AhBl + AlBh (err ~2^-22). PASSES=2: AhBh + AlBh = A*fp16(B).
#define LDA_B    80
#define MAT_B    (128 * LDA_B)
#define STAGE_B  (4 * MAT_B)
#define GEMM_SMEM (2 * STAGE_B)

template<int GATHER, int PASSES>
__device__ __forceinline__ void load_chunk(
    const __half* __restrict__ Ah_g, const __half* __restrict__ Al_g,
    const __half* __restrict__ Bh_g, const __half* __restrict__ Bl_g,
    uint32_t sbase, int mBase, int nBase, int k0, int K, int tid)
{
    const int NSEG = (PASSES == 3) ? 2048 : 1536;   // 4 or 3 matrices
    #pragma unroll
    for (int i = 0; i < 8; i++) {
        int u = tid + i * 256;
        if (u >= NSEG) break;
        int mat = u >> 9;
        int r   = (u >> 2) & 127;
        int seg = u & 3;
        const __half* src;
        int row;
        if (mat < 2) {
            row = mBase + r;
            if (GATHER) {
                int bb = row / 196;
                int t  = row - bb * 196;
                row = bb * 784 + (t / 14) * 56 + (t % 14) * 2;
            }
            src = (mat == 0) ? Ah_g : Al_g;
        } else {
            row = nBase + r;
            src = (mat == 2) ? Bh_g : Bl_g;
        }
        cp_async16(sbase + mat * MAT_B + r * LDA_B + seg * 16,
                   src + (size_t)row * K + k0 + seg * 8);
    }
}

template<int PASSES>
__device__ __forceinline__ void compute_chunk(
    uint32_t stage, float acc[2][8][4], int wm, int wn, int lane)
{
    const int sub    = lane >> 3;
    const int arow_f = (lane & 7) + ((sub & 1) << 3);
    const int akof   = (sub >> 1) << 3;
    const int brow_f = lane & 7;
    const int bkof   = ((lane >> 3) & 1) << 3;

    #pragma unroll
    for (int ks = 0; ks < 2; ks++) {
        const int kb = ks * 16;
        uint32_t Ahf[2][4], Alf[2][4];
        #pragma unroll
        for (int mt = 0; mt < 2; mt++) {
            uint32_t aaddr = stage + (uint32_t)(wm + mt * 16 + arow_f) * LDA_B
                           + (uint32_t)(kb + akof) * 2;
            ldsm_x4(aaddr,         Ahf[mt][0], Ahf[mt][1], Ahf[mt][2], Ahf[mt][3]);
            ldsm_x4(aaddr + MAT_B, Alf[mt][0], Alf[mt][1], Alf[mt][2], Alf[mt][3]);
        }
        #pragma unroll
        for (int nt = 0; nt < 8; nt++) {
            uint32_t baddr = stage + 2 * MAT_B + (uint32_t)(wn + nt * 8 + brow_f) * LDA_B
                           + (uint32_t)(kb + bkof) * 2;
            uint32_t bh0, bh1;
            ldsm_x2(baddr, bh0, bh1);
            if (PASSES == 3) {
                uint32_t bl0, bl1;
                ldsm_x2(baddr + MAT_B, bl0, bl1);
                #pragma unroll
                for (int mt = 0; mt < 2; mt++) {
                    mma16816(acc[mt][nt], Ahf[mt][0], Ahf[mt][1], Ahf[mt][2], Ahf[mt][3], bh0, bh1);
                    mma16816(acc[mt][nt], Ahf[mt][0], Ahf[mt][1], Ahf[mt][2], Ahf[mt][3], bl0, bl1);
                    mma16816(acc[mt][nt], Alf[mt][0], Alf[mt][1], Alf[mt][2], Alf[mt][3], bh0, bh1);
                }
            } else {
                #pragma unroll
                for (int mt = 0; mt < 2; mt++) {
                    mma16816(acc[mt][nt], Ahf[mt][0], Ahf[mt][1], Ahf[mt][2], Ahf[mt][3], bh0, bh1);
                    mma16816(acc[mt][nt], Alf[mt][0], Alf[mt][1], Alf[mt][2], Alf[mt][3], bh0, bh1);
                }
            }
        }
    }
}

template<int GATHER, int PASSES>
__global__ void __launch_bounds__(256) gemm_mma(
    const __half* __restrict__ Ah_g, const __half* __restrict__ Al_g,
    const __half* __restrict__ Bh_g, const __half* __restrict__ Bl_g,
    float* __restrict__ C, int M, int N, int K)
{
    extern __shared__ char gsm[];
    const int tid = threadIdx.x;
    const int wid = tid >> 5, lane = tid & 31;
    const int mBase = blockIdx.y * 128;
    const int nBase = blockIdx.x * 128;
    const int wm = (wid & 3) * 32;
    const int wn = (wid >> 2) * 64;

    const uint32_t sbase = smem_u32(gsm);

    float acc[2][8][4];
    #pragma unroll
    for (int mt = 0; mt < 2; mt++)
        #pragma unroll
        for (int nt = 0; nt < 8; nt++)
            #pragma unroll
            for (int j = 0; j < 4; j++) acc[mt][nt][j] = 0.f;

    const int nc = K >> 5;

    load_chunk<GATHER, PASSES>(Ah_g, Al_g, Bh_g, Bl_g, sbase, mBase, nBase, 0, K, tid);
    cp_commit();

    for (int c = 0; c < nc; c++) {
        if (c + 1 < nc) {
            load_chunk<GATHER, PASSES>(Ah_g, Al_g, Bh_g, Bl_g,
                               sbase + ((c + 1) & 1) * STAGE_B,
                               mBase, nBase, (c + 1) * 32, K, tid);
            cp_commit();
            cp_wait<1>();
        } else {
            cp_wait<0>();
        }
        __syncthreads();
        compute_chunk<PASSES>(sbase + (c & 1) * STAGE_B, acc, wm, wn, lane);
        __syncthreads();
    }

    const uint32_t g  = lane >> 2;
    const uint32_t t4 = lane & 3;
    #pragma unroll
    for (int mt = 0; mt < 2; mt++) {
        #pragma unroll
        for (int nt = 0; nt < 8; nt++) {
            const int col = nBase + wn + nt * 8 + t4 * 2;
            const int r0 = mBase + wm + mt * 16 + g;
            float2 v0 = make_float2(acc[mt][nt][0], acc[mt][nt][1]);
            float2 v1 = make_float2(acc[mt][nt][2], acc[mt][nt][3]);
            *reinterpret_cast<float2*>(C + (size_t)r0 * N + col)       = v0;
            *reinterpret_cast<float2*>(C + (size_t)(r0 + 8) * N + col) = v1;
        }
    }
}

// ---------------------------------------------------------------- column reduce (partial, 64 chunks)
__global__ void __launch_bounds__(256) col_partial(
    const float* __restrict__ Y, float* __restrict__ ps, float* __restrict__ pq,
    int M, int Ncols)
{
    const int col = blockIdx.x * 256 + threadIdx.x;
    const int ch  = blockIdx.y;
    const int per = (M + 63) >> 6;
    const int r0 = ch * per;
    int r1 = r0 + per; if (r1 > M) r1 = M;
    float s = 0.f, s2 = 0.f;
    for (int r = r0; r < r1; r++) {
        float v = Y[(size_t)r * Ncols + col];
        s += v;
        s2 = fmaf(v, v, s2);
    }
    ps[(size_t)ch * Ncols + col] = s;
    pq[(size_t)ch * Ncols + col] = s2;
}

// ---------------------------------------------------------------- reduce 14 chunk-partials -> 1 (DISJOINT output)
__global__ void __launch_bounds__(256) reduce14(
    const float* __restrict__ ps, const float* __restrict__ pq,
    float* __restrict__ ps2, float* __restrict__ pq2, int Ncols)
{
    const int col = blockIdx.x * 256 + threadIdx.x;
    const int by  = blockIdx.y;
    float s = 0.f, q = 0.f;
    #pragma unroll
    for (int c = 0; c < 14; c++) {
        s += ps[(size_t)(by * 14 + c) * Ncols + col];
        q += pq[(size_t)(by * 14 + c) * Ncols + col];
    }
    ps2[(size_t)by * Ncols + col] = s;
    pq2[(size_t)by * Ncols + col] = q;
}

// ---------------------------------------------------------------- BN finalize (nch chunks)
__global__ void __launch_bounds__(256) bn_finalize(
    const float* __restrict__ ps, const float* __restrict__ pq,
    const float* __restrict__ g, const float* __restrict__ b,
    float* __restrict__ scale, float* __restrict__ shift,
    int Ncols, int nch, float invM)
{
    const int col = blockIdx.x * 256 + threadIdx.x;
    float s = 0.f, s2 = 0.f;
    for (int c = 0; c < nch; c++) {
        s  += ps[(size_t)c * Ncols + col];
        s2 += pq[(size_t)c * Ncols + col];
    }
    float m   = s * invM;
    float var = s2 * invM - m * m;
    float sc  = g[col] * rsqrtf(var + EPSV);
    scale[col] = sc;
    shift[col] = b[col] - m * sc;
}

// ---------------------------------------------------------------- K/V prep (raw fp16 split + transpose) + fused column stats
__global__ void __launch_bounds__(256) prep_kv(
    const float* __restrict__ Ykv,
    __half* __restrict__ KH, __half* __restrict__ KL,
    __half* __restrict__ VTH, __half* __restrict__ VTL,
    float* __restrict__ ps, float* __restrict__ pq)
{
    __shared__ __align__(16) __half sVh[64 * 56];
    __shared__ __align__(16) __half sVl[64 * 56];
    __shared__ float pS[10][96], pQ[10][96];

    const int tid = threadIdx.x;
    const int kc = blockIdx.x, h = blockIdx.y, b = blockIdx.z;
    const int kb = kc * 56;
    const int bh = b * HH + h;

    const int f = tid % 24;
    const int rg = tid / 24;

    if (rg < 10) {
        float s4[4] = {0.f, 0.f, 0.f, 0.f};
        float q4[4] = {0.f, 0.f, 0.f, 0.f};
        for (int r = rg; r < 56; r += 10) {
            float4 v = *(reinterpret_cast<const float4*>(
                Ykv + (size_t)(b * NN + kb + r) * OKV + h * 96) + f);
            float vv[4] = {v.x, v.y, v.z, v.w};
            #pragma unroll
            for (int j = 0; j < 4; j++) {
                s4[j] += vv[j];
                q4[j] = fmaf(vv[j], vv[j], q4[j]);
            }
            if (f < 8) {
                int d = f * 4;
                __half hh[4], ll[4];
                #pragma unroll
                for (int j = 0; j < 4; j++) {
                    hh[j] = __float2half(vv[j]);
                    ll[j] = __float2half(vv[j] - __half2float(hh[j]));
                }
                size_t base = ((size_t)bh * NN + kb + r) * 32 + d;
                reinterpret_cast<__half2*>(KH + base)[0] = __halves2half2(hh[0], hh[1]);
                reinterpret_cast<__half2*>(KH + base)[1] = __halves2half2(hh[2], hh[3]);
                reinterpret_cast<__half2*>(KL + base)[0] = __halves2half2(ll[0], ll[1]);
                reinterpret_cast<__half2*>(KL + base)[1] = __halves2half2(ll[2], ll[3]);
            } else {
                int d = (f - 8) * 4;
                #pragma unroll
                for (int j = 0; j < 4; j++) {
                    __half hh = __float2half(vv[j]);
                    sVh[(d + j) * 56 + r] = hh;
                    sVl[(d + j) * 56 + r] = __float2half(vv[j] - __half2float(hh));
                }
            }
        }
        #pragma unroll
        for (int j = 0; j < 4; j++) { pS[rg][f * 4 + j] = s4[j]; pQ[rg][f * 4 + j] = q4[j]; }
    }
    __syncthreads();

    if (tid < 96) {
        float s = 0.f, q = 0.f;
        #pragma unroll
        for (int gi = 0; gi < 10; gi++) { s += pS[gi][tid]; q += pQ[gi][tid]; }
        size_t chunk = (size_t)(b * 14 + kc);
        ps[chunk * OKV + h * 96 + tid] = s;
        pq[chunk * OKV + h * 96 + tid] = q;
    }

    for (int u = tid; u < 64 * 7; u += 256) {
        int d = u / 7, seg = u - d * 7;
        uint4 vh = *reinterpret_cast<const uint4*>(&sVh[d * 56 + seg * 8]);
        uint4 vl = *reinterpret_cast<const uint4*>(&sVl[d * 56 + seg * 8]);
        size_t base = ((size_t)bh * 64 + d) * NN + kb + seg * 8;
        *reinterpret_cast<uint4*>(VTH + base) = vh;
        *reinterpret_cast<uint4*>(VTL + base) = vl;
    }
}

// ---------------------------------------------------------------- attention (tensor-core, raw K/V, folded BN)
__device__ __forceinline__ float hswish(float x) {
    float t = fminf(fmaxf(x + 3.f, 0.f), 6.f);
    return x * t * (1.f / 6.f);
}

// smem byte offsets
#define AQP 80
#define AVP 144
#define K_ST 4480
#define V_ST 9216
#define O_QH 0
#define O_QL 5120
#define O_KH 10240
#define O_KL 19200
#define O_VH 28160
#define O_VL 46592
#define O_PH 65024
#define O_PL 74240
#define O_S  83456
#define O_BH 94432
#define O_SCQ 97568
#define O_SHQ 97696
#define O_SCK 97824
#define O_SCV 97952
#define O_SHV 98208
#define O_MR 98464
#define O_LR 98720
#define O_AR 98976
#define ATTN_SMEM 99232

__global__ void __launch_bounds__(256) attn_mma2(
    const __half* __restrict__ KHg, const __half* __restrict__ KLg,
    const __half* __restrict__ VTHg, const __half* __restrict__ VTLg,
    const float* __restrict__ Yq,
    const float* __restrict__ scq,  const float* __restrict__ shq,
    const float* __restrict__ sckv, const float* __restrict__ shkv,
    const float* __restrict__ biases, const int* __restrict__ bidx,
    __half* __restrict__ Yoh, __half* __restrict__ Yol)
{
    extern __shared__ char sm[];
    __half* Qh = reinterpret_cast<__half*>(sm + O_QH);
    __half* Ql = reinterpret_cast<__half*>(sm + O_QL);
    __half* Ph = reinterpret_cast<__half*>(sm + O_PH);
    __half* Pl = reinterpret_cast<__half*>(sm + O_PL);
    float* S    = reinterpret_cast<float*>(sm + O_S);
    float* bh   = reinterpret_cast<float*>(sm + O_BH);
    float* scqh = reinterpret_cast<float*>(sm + O_SCQ);
    float* shqh = reinterpret_cast<float*>(sm + O_SHQ);
    float* sckh = reinterpret_cast<float*>(sm + O_SCK);
    float* scvh = reinterpret_cast<float*>(sm + O_SCV);
    float* shvh = reinterpret_cast<float*>(sm + O_SHV);
    float* mrow = reinterpret_cast<float*>(sm + O_MR);
    float* lrow = reinterpret_cast<float*>(sm + O_LR);
    float* arow = reinterpret_cast<float*>(sm + O_AR);

    const int tid = threadIdx.x;
    const int wid = tid >> 5, lane = tid & 31;
    const int qg = blockIdx.x, h = blockIdx.y, b = blockIdx.z;
    const int bh_idx = b * HH + h;

    const __half* KHb = KHg + (size_t)bh_idx * NN * 32;
    const __half* KLb = KLg + (size_t)bh_idx * NN * 32;
    const __half* VHb = VTHg + (size_t)bh_idx * 64 * NN;
    const __half* VLb = VTLg + (size_t)bh_idx * 64 * NN;

    const uint32_t sbase = smem_u32(sm);
    const uint32_t uQH = sbase + O_QH, uQL = sbase + O_QL;
    const uint32_t uKH = sbase + O_KH, uKL = sbase + O_KL;
    const uint32_t uVH = sbase + O_VH, uVL = sbase + O_VL;
    const uint32_t uPH = sbase + O_PH, uPL = sbase + O_PL;

    if (tid < 32) {
        scqh[tid] = scq[h * 32 + tid];
        shqh[tid] = shq[h * 32 + tid];
        sckh[tid] = sckv[h * 96 + tid];
    } else if (tid < 96) {
        int d = tid - 32;
        scvh[d] = sckv[h * 96 + 32 + d];
        shvh[d] = shkv[h * 96 + 32 + d];
    }
    for (int i = tid; i < 784; i += 256) bh[i] = biases[h * 784 + i];
    if (tid < 64) { mrow[tid] = -1e30f; lrow[tid] = 0.f; arow[tid] = 0.f; }
    for (int u = tid; u < 150; u += 256) {
        int m = u / 75, w = u - m * 75;
        int r = 49 + w / 5, sgm = w - (w / 5) * 5;
        uint32_t off = (m == 0 ? O_QH : O_QL) + (uint32_t)r * AQP + sgm * 16;
        *reinterpret_cast<uint4*>(sm + off) = make_uint4(0, 0, 0, 0);
    }
    for (int u = tid; u < 512; u += 256) {
        int m = u >> 8, w = u & 255;
        int st = w >> 7, w2 = w & 127;
        int d = w2 >> 1, half = w2 & 1;
        uint32_t off = (m == 0 ? O_VH : O_VL) + st * V_ST + (uint32_t)d * AVP + 112 + half * 16;
        *reinterpret_cast<uint4*>(sm + off) = make_uint4(0, 0, 0, 0);
    }
    for (int u = tid; u < 1152; u += 256)
        reinterpret_cast<uint4*>(sm + O_PH)[u] = make_uint4(0, 0, 0, 0);
    __syncthreads();

    for (int e = tid; e < 49 * 32; e += 256) {
        int r = e >> 5, d = e & 31;
        float v = fmaf(Yq[(size_t)(b * NQ + qg * 49 + r) * OQ + h * 32 + d], scqh[d], shqh[d]) * sckh[d];
        __half hh = __float2half(v);
        Qh[r * 40 + d] = hh;
        Ql[r * 40 + d] = __float2half(v - __half2float(hh));
    }

    auto issue_chunk = [&](int kc) {
        const int st = kc & 1;
        const int kb = kc * 56;
        #pragma unroll
        for (int i = 0; i < 6; i++) {
            int u = tid + i * 256;
            if (u >= 1344) break;
            if (u < 448) {
                int hi = (u < 224);
                int w = hi ? u : u - 224;
                int r = w >> 2, seg = w & 3;
                const __half* src = (hi ? KHb : KLb) + (size_t)(kb + r) * 32 + seg * 8;
                uint32_t dst = (hi ? uKH : uKL) + st * K_ST + (uint32_t)r * AQP + seg * 16;
                cp_async16(dst, src);
            } else {
                int v = u - 448;
                int hi = (v < 448);
                int w = hi ? v : v - 448;
                int d = w / 7, seg = w - d * 7;
                const __half* src = (hi ? VHb : VLb) + (size_t)d * NN + kb + seg * 8;
                uint32_t dst = (hi ? uVH : uVL) + st * V_ST + (uint32_t)d * AVP + seg * 16;
                cp_async16(dst, src);
            }
        }
        cp_commit();
    };

    const int mw  = wid >> 1;
    const int nt0 = (wid & 1) * 4;
    const int ntn = (wid & 1) ? 3 : 4;
    const int g   = lane >> 2, t4 = lane & 3;
    const int sub = lane >> 3;
    const int arow_f = (lane & 7) + ((sub & 1) << 3);
    const int akof   = (sub >> 1) << 3;
    const int brow_f = lane & 7;
    const int bkof   = ((lane >> 3) & 1) << 3;
    const int sr = (tid < 196) ? (tid >> 2) : 48;
    const int sq = tid & 3;
    const bool sact = (tid < 196);

    float accp[4][4];
    #pragma unroll
    for (int i = 0; i < 4; i++)
        #pragma unroll
        for (int j = 0; j < 4; j++) accp[i][j] = 0.f;

    issue_chunk(0);

    for (int kc = 0; kc < 14; kc++) {
        const int st = kc & 1;
        const int kb = kc * 56;

        cp_wait<0>();
        __syncthreads();

        if (kc + 1 < 14) issue_chunk(kc + 1);

        // ---- QK mma + bias + write S
        {
            float acc[4][4];
            #pragma unroll
            for (int i = 0; i < 4; i++)
                #pragma unroll
                for (int j = 0; j < 4; j++) acc[i][j] = 0.f;
            #pragma unroll
            for (int ks = 0; ks < 2; ks++) {
                uint32_t aoff = (uint32_t)(mw * 16 + arow_f) * AQP + (uint32_t)(ks * 16 + akof) * 2;
                uint32_t Ahf[4], Alf[4];
                ldsm_x4(uQH + aoff, Ahf[0], Ahf[1], Ahf[2], Ahf[3]);
                ldsm_x4(uQL + aoff, Alf[0], Alf[1], Alf[2], Alf[3]);
                for (int nti = 0; nti < ntn; nti++) {
                    int nt = nt0 + nti;
                    uint32_t boff = st * K_ST + (uint32_t)(nt * 8 + brow_f) * AQP
                                  + (uint32_t)(ks * 16 + bkof) * 2;
                    uint32_t bh0, bh1, bl0, bl1;
                    ldsm_x2(uKH + boff, bh0, bh1);
                    ldsm_x2(uKL + boff, bl0, bl1);
                    mma16816(acc[nti], Ahf[0], Ahf[1], Ahf[2], Ahf[3], bh0, bh1);
                    mma16816(acc[nti], Ahf[0], Ahf[1], Ahf[2], Ahf[3], bl0, bl1);
                    mma16816(acc[nti], Alf[0], Alf[1], Alf[2], Alf[3], bh0, bh1);
                }
            }
            const int r0 = mw * 16 + g;
            for (int nti = 0; nti < ntn; nti++) {
                int nt = nt0 + nti;
                int c0 = nt * 8 + t4 * 2;
                if (r0 < 49) {
                    int2 id = *reinterpret_cast<const int2*>(
                        &bidx[(size_t)(qg * 49 + r0) * NN + kb + c0]);
                    float2 s0 = make_float2(fmaf(acc[nti][0], SCALE_QK, bh[id.x]),
                                            fmaf(acc[nti][1], SCALE_QK, bh[id.y]));
                    *reinterpret_cast<float2*>(&S[r0 * 56 + c0]) = s0;
                }
                if (r0 + 8 < 49) {
                    int2 id = *reinterpret_cast<const int2*>(
                        &bidx[(size_t)(qg * 49 + r0 + 8) * NN + kb + c0]);
                    float2 s1 = make_float2(fmaf(acc[nti][2], SCALE_QK, bh[id.x]),
                                            fmaf(acc[nti][3], SCALE_QK, bh[id.y]));
                    *reinterpret_cast<float2*>(&S[(r0 + 8) * 56 + c0]) = s1;
                }
            }
        }
        __syncthreads();

        // ---- online softmax, write P fp16 hi/lo
        {
            float xv[14];
            float cm = -1e30f;
            #pragma unroll
            for (int j = 0; j < 14; j++) {
                xv[j] = S[sr * 56 + sq + 4 * j];
                cm = fmaxf(cm, xv[j]);
            }
            cm = fmaxf(cm, __shfl_xor_sync(0xffffffffu, cm, 1));
            cm = fmaxf(cm, __shfl_xor_sync(0xffffffffu, cm, 2));
            float mo = mrow[sr];
            float mn = fmaxf(mo, cm);
            float cs = 0.f;
            #pragma unroll
            for (int j = 0; j < 14; j++) {
                float p = __expf(xv[j] - mn);
                xv[j] = p;
                cs += p;
            }
            cs += __shfl_xor_sync(0xffffffffu, cs, 1);
            cs += __shfl_xor_sync(0xffffffffu, cs, 2);
            if (sact) {
                #pragma unroll
                for (int j = 0; j < 14; j++) {
                    __half ph = __float2half(xv[j]);
                    Ph[sr * 72 + sq + 4 * j] = ph;
                    Pl[sr * 72 + sq + 4 * j] = __float2half(xv[j] - __half2float(ph));
                }
                if (sq == 0) {
                    float a = __expf(mo - mn);
                    arow[sr] = a;
                    lrow[sr] = lrow[sr] * a + cs;
                    mrow[sr] = mn;
                }
            }
        }
        __syncthreads();

        // ---- PV mma with rescale
        {
            const int r0 = mw * 16 + g;
            float a0 = arow[r0], a1 = arow[r0 + 8];
            #pragma unroll
            for (int nti = 0; nti < 4; nti++) {
                accp[nti][0] *= a0; accp[nti][1] *= a0;
                accp[nti][2] *= a1; accp[nti][3] *= a1;
            }
            #pragma unroll
            for (int ks = 0; ks < 4; ks++) {
                uint32_t aoff = (uint32_t)(mw * 16 + arow_f) * AVP + (uint32_t)(ks * 16 + akof) * 2;
                uint32_t Phf[4], Plf[4];
                ldsm_x4(uPH + aoff, Phf[0], Phf[1], Phf[2], Phf[3]);
                ldsm_x4(uPL + aoff, Plf[0], Plf[1], Plf[2], Plf[3]);
                #pragma unroll
                for (int nti = 0; nti < 4; nti++) {
                    int dt8 = ((wid & 1) * 4 + nti) * 8;
                    uint32_t boff = st * V_ST + (uint32_t)(dt8 + brow_f) * AVP
                                  + (uint32_t)(ks * 16 + bkof) * 2;
                    uint32_t vh0, vh1, vl0, vl1;
                    ldsm_x2(uVH + boff, vh0, vh1);
                    ldsm_x2(uVL + boff, vl0, vl1);
                    mma16816(accp[nti], Phf[0], Phf[1], Phf[2], Phf[3], vh0, vh1);
                    mma16816(accp[nti], Phf[0], Phf[1], Phf[2], Phf[3], vl0, vl1);
                    mma16816(accp[nti], Plf[0], Plf[1], Plf[2], Plf[3], vh0, vh1);
                }
            }
        }
    }

    // ---- epilogue: out = hswish(scv * acc/l + shv), fp16 hi/lo store
    const int r0 = mw * 16 + g;
    #pragma unroll
    for (int half = 0; half < 2; half++) {
        int rr = r0 + half * 8;
        if (rr >= 49) continue;
        float inv = 1.0f / lrow[rr];
        int q = qg * 49 + rr;
        #pragma unroll
        for (int nti = 0; nti < 4; nti++) {
            int c0 = (wid & 1) * 32 + nti * 8 + t4 * 2;
            float o0 = hswish(fmaf(accp[nti][half * 2 + 0] * inv, scvh[c0],     shvh[c0]));
            float o1 = hswish(fmaf(accp[nti][half * 2 + 1] * inv, scvh[c0 + 1], shvh[c0 + 1]));
            __half h0 = __float2half(o0);
            __half h1 = __float2half(o1);
            __half l0 = __float2half(o0 - __half2float(h0));
            __half l1 = __float2half(o1 - __half2float(h1));
            size_t base = (size_t)(b * NQ + q) * DH + h * 64 + c0;
            *reinterpret_cast<__half2*>(Yoh + base) = __halves2half2(h0, h1);
            *reinterpret_cast<__half2*>(Yol + base) = __halves2half2(l0, l1);
        }
    }
}

// ---------------------------------------------------------------- final BN apply (float4)
__global__ void __launch_bounds__(256) bn_apply4(
    const float4* __restrict__ Y, const float* __restrict__ scale,
    const float* __restrict__ shift, float4* __restrict__ out, int Ncols4)
{
    const int i = blockIdx.x * 256 + threadIdx.x;
    float4 v = Y[i];
    const int c = (i % Ncols4) * 4;
    out[i] = make_float4(fmaf(v.x, scale[c + 0], shift[c + 0]),
                         fmaf(v.y, scale[c + 1], shift[c + 1]),
                         fmaf(v.z, scale[c + 2], shift[c + 2]),
                         fmaf(v.w, scale[c + 3], shift[c + 3]));
}

// ---------------------------------------------------------------- launch
extern "C" void kernel_launch(void* const* d_in, const int* in_sizes, int n_in,
                              void* d_out, int out_size)
{
    const float* x    = (const float*)d_in[0];
    const float* W_kv = (const float*)d_in[1];
    const float* gkv  = (const float*)d_in[2];
    const float* bkv  = (const float*)d_in[3];
    const float* W_q  = (const float*)d_in[4];
    const float* gq   = (const float*)d_in[5];
    const float* bq   = (const float*)d_in[6];
    const float* W_p  = (const float*)d_in[7];
    const float* gp   = (const float*)d_in[8];
    const float* bp   = (const float*)d_in[9];
    const float* ab   = (const float*)d_in[10];
    const int*   bidx = (const int*)d_in[11];
    float* out = (float*)d_out;

    float *Ykv, *Yq, *Yp, *ps, *pq, *ps2, *pq2;
    float *sckv, *shkv, *scq, *shq, *scp, *shp;
    __half *xh, *xl, *Wkvh, *Wkvl, *Wqh, *Wql, *Wph, *Wpl, *Yoh, *Yol;
    __half *KH, *KL, *VTH, *VTL;
    cudaGetSymbolAddress((void**)&Ykv, g_Ykv);
    cudaGetSymbolAddress((void**)&Yq,  g_Yq);
    cudaGetSymbolAddress((void**)&Yp,  g_Yp);
    cudaGetSymbolAddress((void**)&ps,  g_ps);
    cudaGetSymbolAddress((void**)&pq,  g_pq);
    cudaGetSymbolAddress((void**)&ps2, g_ps2);
    cudaGetSymbolAddress((void**)&pq2, g_pq2);
    cudaGetSymbolAddress((void**)&sckv, g_sc_kv);
    cudaGetSymbolAddress((void**)&shkv, g_sh_kv);
    cudaGetSymbolAddress((void**)&scq,  g_sc_q);
    cudaGetSymbolAddress((void**)&shq,  g_sh_q);
    cudaGetSymbolAddress((void**)&scp,  g_sc_p);
    cudaGetSymbolAddress((void**)&shp,  g_sh_p);
    cudaGetSymbolAddress((void**)&xh,   g_xh);
    cudaGetSymbolAddress((void**)&xl,   g_xl);
    cudaGetSymbolAddress((void**)&Wkvh, g_Wkvh);
    cudaGetSymbolAddress((void**)&Wkvl, g_Wkvl);
    cudaGetSymbolAddress((void**)&Wqh,  g_Wqh);
    cudaGetSymbolAddress((void**)&Wql,  g_Wql);
    cudaGetSymbolAddress((void**)&Wph,  g_Wph);
    cudaGetSymbolAddress((void**)&Wpl,  g_Wpl);
    cudaGetSymbolAddress((void**)&Yoh,  g_Yoh);
    cudaGetSymbolAddress((void**)&Yol,  g_Yol);
    cudaGetSymbolAddress((void**)&KH,   g_KH);
    cudaGetSymbolAddress((void**)&KL,   g_KL);
    cudaGetSymbolAddress((void**)&VTH,  g_VTH);
    cudaGetSymbolAddress((void**)&VTL,  g_VTL);

    cudaFuncSetAttribute((const void*)gemm_mma<0,2>, cudaFuncAttributeMaxDynamicSharedMemorySize, GEMM_SMEM);
    cudaFuncSetAttribute((const void*)gemm_mma<1,2>, cudaFuncAttributeMaxDynamicSharedMemorySize, GEMM_SMEM);
    cudaFuncSetAttribute(attn_mma2, cudaFuncAttributeMaxDynamicSharedMemorySize, ATTN_SMEM);

    // 0) fp16 hi/lo splits
    cvt_split4<<<(unsigned)(((size_t)MKV * CC / 4 + 255) / 256), 256>>>(x, xh, xl, (size_t)MKV * CC / 4);
    cvt_split4<<<(unsigned)(((size_t)OKV * CC / 4 + 255) / 256), 256>>>(W_kv, Wkvh, Wkvl, (size_t)OKV * CC / 4);
    cvt_split4<<<(unsigned)(((size_t)OQ  * CC / 4 + 255) / 256), 256>>>(W_q, Wqh, Wql, (size_t)OQ * CC / 4);
    cvt_split4<<<(unsigned)(((size_t)OP  * DH / 4 + 255) / 256), 256>>>(W_p, Wph, Wpl, (size_t)OP * DH / 4);

    // 1) kv GEMM (2-pass fp16) ; prep ; reduce ; BN finalize
    gemm_mma<0,2><<<dim3(OKV / 128, MKV / 128), 256, GEMM_SMEM>>>(xh, xl, Wkvh, Wkvl, Ykv, MKV, OKV, CC);
    prep_kv<<<dim3(14, HH, BB), 256>>>(Ykv, KH, KL, VTH, VTL, ps, pq);
    reduce14<<<dim3(OKV / 256, 64), 256>>>(ps, pq, ps2, pq2, OKV);
    bn_finalize<<<OKV / 256, 256>>>(ps2, pq2, gkv, bkv, sckv, shkv, OKV, 64, 1.f / MKV);

    // 2) q = xq @ W_q^T (gathered rows, 2-pass fp16)
    gemm_mma<1,2><<<dim3(OQ / 128, MQ / 128), 256, GEMM_SMEM>>>(xh, xl, Wqh, Wql, Yq, MQ, OQ, CC);
    col_partial<<<dim3(OQ / 256, 64), 256>>>(Yq, ps, pq, MQ, OQ);
    bn_finalize<<<OQ / 256, 256>>>(ps, pq, gq, bq, scq, shq, OQ, 64, 1.f / MQ);

    // 3) attention + hard-swish
    attn_mma2<<<dim3(4, HH, BB), 256, ATTN_SMEM>>>(
        KH, KL, VTH, VTL, Yq, scq, shq, sckv, shkv, ab, bidx, Yoh, Yol);

    // 4) proj (2-pass fp16)
    gemm_mma<0,2><<<dim3(OP / 128, MQ / 128), 256, GEMM_SMEM>>>(Yoh, Yol, Wph, Wpl, Yp, MQ, OP, DH);
    col_partial<<<dim3(OP / 256, 64), 256>>>(Yp, ps, pq, MQ, OP);
    bn_finalize<<<OP / 256, 256>>>(ps, pq, gp, bp, scp, shp, OP, 64, 1.f / MQ);
    bn_apply4<<<(MQ * OP / 4) / 256, 256>>>(
        reinterpret_cast<const float4*>(Yp), scp, shp,
        reinterpret_cast<float4*>(out), OP / 4);
}

// round 17
// speedup vs baseline: 1.4085x; 1.1064x over previous
#include <cuda_runtime.h>
#include <cuda_fp16.h>
#include <cstdint>

// ---------------------------------------------------------------- constants
#define EPSV      1e-5f
#define SCALE_QK  0.17677669529663687f   // 1/sqrt(32)

#define BB   64
#define NN   784
#define NQ   196
#define CC   512
#define HH   16
#define OKV  1536
#define OQ   512
#define DH   1024
#define OP   768
#define MKV  (BB*NN)  // 50176
#define MQ   (BB*NQ)  // 12544

// ---------------------------------------------------------------- scratch
__device__ float g_Ykv[(size_t)MKV * OKV];
__device__ float g_Yq [(size_t)MQ  * OQ];
__device__ float g_Yp [(size_t)MQ  * OP];
__device__ float g_ps [(size_t)(BB * 14) * OKV];
__device__ float g_pq [(size_t)(BB * 14) * OKV];
__device__ float g_ps2[64 * OKV];
__device__ float g_pq2[64 * OKV];
__device__ float g_sc_kv[OKV], g_sh_kv[OKV];
__device__ float g_sc_q [OQ],  g_sh_q [OQ];
__device__ float g_sc_p [OP],  g_sh_p [OP];

// fp16 split operands
__device__ __half g_xh [(size_t)MKV * CC],  g_xl [(size_t)MKV * CC];
__device__ __half g_Wkvh[(size_t)OKV * CC], g_Wkvl[(size_t)OKV * CC];
__device__ __half g_Wqh [(size_t)OQ  * CC], g_Wql [(size_t)OQ  * CC];
__device__ __half g_Wph [(size_t)OP  * DH], g_Wpl [(size_t)OP  * DH];
__device__ __half g_Yoh [(size_t)MQ  * DH], g_Yol [(size_t)MQ  * DH];

// prepped attention operands (RAW values, fp16 split; V transposed)
__device__ __half g_KH [(size_t)BB * HH * NN * 32], g_KL [(size_t)BB * HH * NN * 32];
__device__ __half g_VTH[(size_t)BB * HH * 64 * NN], g_VTL[(size_t)BB * HH * 64 * NN];

// ---------------------------------------------------------------- helpers
__device__ __forceinline__ uint32_t smem_u32(const void* p) {
    uint32_t a;
    asm("{ .reg .u64 t; cvta.to.shared.u64 t, %1; cvt.u32.u64 %0, t; }" : "=r"(a) : "l"(p));
    return a;
}
__device__ __forceinline__ void cp_async16(uint32_t dst, const void* src) {
    asm volatile("cp.async.cg.shared.global [%0], [%1], 16;" :: "r"(dst), "l"(src) : "memory");
}
__device__ __forceinline__ void cp_commit() {
    asm volatile("cp.async.commit_group;" ::: "memory");
}
template<int N>
__device__ __forceinline__ void cp_wait() {
    asm volatile("cp.async.wait_group %0;" :: "n"(N) : "memory");
}
__device__ __forceinline__ void mma16816(float* c, uint32_t a0, uint32_t a1,
                                         uint32_t a2, uint32_t a3,
                                         uint32_t b0, uint32_t b1) {
    asm volatile(
        "mma.sync.aligned.m16n8k16.row.col.f32.f16.f16.f32 "
        "{%0,%1,%2,%3}, {%4,%5,%6,%7}, {%8,%9}, {%0,%1,%2,%3};"
        : "+f"(c[0]), "+f"(c[1]), "+f"(c[2]), "+f"(c[3])
        : "r"(a0), "r"(a1), "r"(a2), "r"(a3), "r"(b0), "r"(b1));
}
__device__ __forceinline__ void ldsm_x4(uint32_t addr, uint32_t& r0, uint32_t& r1,
                                        uint32_t& r2, uint32_t& r3) {
    asm volatile("ldmatrix.sync.aligned.m8n8.x4.shared.b16 {%0,%1,%2,%3}, [%4];"
        : "=r"(r0), "=r"(r1), "=r"(r2), "=r"(r3) : "r"(addr));
}
__device__ __forceinline__ void ldsm_x2(uint32_t addr, uint32_t& r0, uint32_t& r1) {
    asm volatile("ldmatrix.sync.aligned.m8n8.x2.shared.b16 {%0,%1}, [%2];"
        : "=r"(r0), "=r"(r1) : "r"(addr));
}

// ---------------------------------------------------------------- fp32 -> fp16 hi/lo split
__global__ void __launch_bounds__(256) cvt_split4(
    const float* __restrict__ X, __half* __restrict__ H,
    __half* __restrict__ L, size_t n4)
{
    size_t i = (size_t)blockIdx.x * 256 + threadIdx.x;
    if (i >= n4) return;
    float4 v = reinterpret_cast<const float4*>(X)[i];
    __half hx = __float2half(v.x);
    __half hy = __float2half(v.y);
    __half hz = __float2half(v.z);
    __half hw = __float2half(v.w);
    __half lx = __float2half(v.x - __half2float(hx));
    __half ly = __float2half(v.y - __half2float(hy));
    __half lz = __float2half(v.z - __half2float(hz));
    __half lw = __float2half(v.w - __half2float(hw));
    reinterpret_cast<__half2*>(H)[2 * i]     = __halves2half2(hx, hy);
    reinterpret_cast<__half2*>(H)[2 * i + 1] = __halves2half2(hz, hw);
    reinterpret_cast<__half2*>(L)[2 * i]     = __halves2half2(lx, ly);
    reinterpret_cast<__half2*>(L)[2 * i + 1] = __halves2half2(lz, lw);
}

// ---------------------------------------------------------------- mma.sync fp16-split GEMM
// PASSES=3: AhBh+AhBl+AlBh. PASSES=2: AhBh+AlBh = A*fp16(B). PASSES=1: AhBh.
#define LDA_B    80
#define MAT_B    (128 * LDA_B)
#define STAGE_B  (4 * MAT_B)
#define GEMM_SMEM (2 * STAGE_B)

template<int GATHER, int PASSES>
__device__ __forceinline__ void load_chunk(
    const __half* __restrict__ Ah_g, const __half* __restrict__ Al_g,
    const __half* __restrict__ Bh_g, const __half* __restrict__ Bl_g,
    uint32_t sbase, int mBase, int nBase, int k0, int K, int tid)
{
    const int NSEG = (PASSES == 3) ? 2048 : (PASSES == 2 ? 1536 : 1024);
    #pragma unroll
    for (int i = 0; i < 8; i++) {
        int u = tid + i * 256;
        if (u >= NSEG) break;
        int mat;
        if (PASSES == 1) mat = (u < 512) ? 0 : 2;     // Ah, Bh only
        else             mat = u >> 9;
        int r   = (u >> 2) & 127;
        int seg = u & 3;
        const __half* src;
        int row;
        if (mat < 2) {
            row = mBase + r;
            if (GATHER) {
                int bb = row / 196;
                int t  = row - bb * 196;
                row = bb * 784 + (t / 14) * 56 + (t % 14) * 2;
            }
            src = (mat == 0) ? Ah_g : Al_g;
        } else {
            row = nBase + r;
            src = (mat == 2) ? Bh_g : Bl_g;
        }
        cp_async16(sbase + mat * MAT_B + r * LDA_B + seg * 16,
                   src + (size_t)row * K + k0 + seg * 8);
    }
}

template<int PASSES>
__device__ __forceinline__ void compute_chunk(
    uint32_t stage, float acc[2][8][4], int wm, int wn, int lane)
{
    const int sub    = lane >> 3;
    const int arow_f = (lane & 7) + ((sub & 1) << 3);
    const int akof   = (sub >> 1) << 3;
    const int brow_f = lane & 7;
    const int bkof   = ((lane >> 3) & 1) << 3;

    #pragma unroll
    for (int ks = 0; ks < 2; ks++) {
        const int kb = ks * 16;
        uint32_t Ahf[2][4], Alf[2][4];
        #pragma unroll
        for (int mt = 0; mt < 2; mt++) {
            uint32_t aaddr = stage + (uint32_t)(wm + mt * 16 + arow_f) * LDA_B
                           + (uint32_t)(kb + akof) * 2;
            ldsm_x4(aaddr, Ahf[mt][0], Ahf[mt][1], Ahf[mt][2], Ahf[mt][3]);
            if (PASSES >= 2)
                ldsm_x4(aaddr + MAT_B, Alf[mt][0], Alf[mt][1], Alf[mt][2], Alf[mt][3]);
        }
        #pragma unroll
        for (int nt = 0; nt < 8; nt++) {
            uint32_t baddr = stage + 2 * MAT_B + (uint32_t)(wn + nt * 8 + brow_f) * LDA_B
                           + (uint32_t)(kb + bkof) * 2;
            uint32_t bh0, bh1;
            ldsm_x2(baddr, bh0, bh1);
            if (PASSES == 3) {
                uint32_t bl0, bl1;
                ldsm_x2(baddr + MAT_B, bl0, bl1);
                #pragma unroll
                for (int mt = 0; mt < 2; mt++) {
                    mma16816(acc[mt][nt], Ahf[mt][0], Ahf[mt][1], Ahf[mt][2], Ahf[mt][3], bh0, bh1);
                    mma16816(acc[mt][nt], Ahf[mt][0], Ahf[mt][1], Ahf[mt][2], Ahf[mt][3], bl0, bl1);
                    mma16816(acc[mt][nt], Alf[mt][0], Alf[mt][1], Alf[mt][2], Alf[mt][3], bh0, bh1);
                }
            } else if (PASSES == 2) {
                #pragma unroll
                for (int mt = 0; mt < 2; mt++) {
                    mma16816(acc[mt][nt], Ahf[mt][0], Ahf[mt][1], Ahf[mt][2], Ahf[mt][3], bh0, bh1);
                    mma16816(acc[mt][nt], Alf[mt][0], Alf[mt][1], Alf[mt][2], Alf[mt][3], bh0, bh1);
                }
            } else {
                #pragma unroll
                for (int mt = 0; mt < 2; mt++)
                    mma16816(acc[mt][nt], Ahf[mt][0], Ahf[mt][1], Ahf[mt][2], Ahf[mt][3], bh0, bh1);
            }
        }
    }
}

template<int GATHER, int PASSES>
__global__ void __launch_bounds__(256) gemm_mma(
    const __half* __restrict__ Ah_g, const __half* __restrict__ Al_g,
    const __half* __restrict__ Bh_g, const __half* __restrict__ Bl_g,
    float* __restrict__ C, int M, int N, int K)
{
    extern __shared__ char gsm[];
    const int tid = threadIdx.x;
    const int wid = tid >> 5, lane = tid & 31;
    const int mBase = blockIdx.y * 128;
    const int nBase = blockIdx.x * 128;
    const int wm = (wid & 3) * 32;
    const int wn = (wid >> 2) * 64;

    const uint32_t sbase = smem_u32(gsm);

    float acc[2][8][4];
    #pragma unroll
    for (int mt = 0; mt < 2; mt++)
        #pragma unroll
        for (int nt = 0; nt < 8; nt++)
            #pragma unroll
            for (int j = 0; j < 4; j++) acc[mt][nt][j] = 0.f;

    const int nc = K >> 5;

    load_chunk<GATHER, PASSES>(Ah_g, Al_g, Bh_g, Bl_g, sbase, mBase, nBase, 0, K, tid);
    cp_commit();

    for (int c = 0; c < nc; c++) {
        if (c + 1 < nc) {
            load_chunk<GATHER, PASSES>(Ah_g, Al_g, Bh_g, Bl_g,
                               sbase + ((c + 1) & 1) * STAGE_B,
                               mBase, nBase, (c + 1) * 32, K, tid);
            cp_commit();
            cp_wait<1>();
        } else {
            cp_wait<0>();
        }
        __syncthreads();
        compute_chunk<PASSES>(sbase + (c & 1) * STAGE_B, acc, wm, wn, lane);
        __syncthreads();
    }

    const uint32_t g  = lane >> 2;
    const uint32_t t4 = lane & 3;
    #pragma unroll
    for (int mt = 0; mt < 2; mt++) {
        #pragma unroll
        for (int nt = 0; nt < 8; nt++) {
            const int col = nBase + wn + nt * 8 + t4 * 2;
            const int r0 = mBase + wm + mt * 16 + g;
            float2 v0 = make_float2(acc[mt][nt][0], acc[mt][nt][1]);
            float2 v1 = make_float2(acc[mt][nt][2], acc[mt][nt][3]);
            *reinterpret_cast<float2*>(C + (size_t)r0 * N + col)       = v0;
            *reinterpret_cast<float2*>(C + (size_t)(r0 + 8) * N + col) = v1;
        }
    }
}

// ---------------------------------------------------------------- column reduce (partial, 64 chunks)
__global__ void __launch_bounds__(256) col_partial(
    const float* __restrict__ Y, float* __restrict__ ps, float* __restrict__ pq,
    int M, int Ncols)
{
    const int col = blockIdx.x * 256 + threadIdx.x;
    const int ch  = blockIdx.y;
    const int per = (M + 63) >> 6;
    const int r0 = ch * per;
    int r1 = r0 + per; if (r1 > M) r1 = M;
    float s = 0.f, s2 = 0.f;
    for (int r = r0; r < r1; r++) {
        float v = Y[(size_t)r * Ncols + col];
        s += v;
        s2 = fmaf(v, v, s2);
    }
    ps[(size_t)ch * Ncols + col] = s;
    pq[(size_t)ch * Ncols + col] = s2;
}

// ---------------------------------------------------------------- reduce 14 chunk-partials -> 1 (DISJOINT output)
__global__ void __launch_bounds__(256) reduce14(
    const float* __restrict__ ps, const float* __restrict__ pq,
    float* __restrict__ ps2, float* __restrict__ pq2, int Ncols)
{
    const int col = blockIdx.x * 256 + threadIdx.x;
    const int by  = blockIdx.y;
    float s = 0.f, q = 0.f;
    #pragma unroll
    for (int c = 0; c < 14; c++) {
        s += ps[(size_t)(by * 14 + c) * Ncols + col];
        q += pq[(size_t)(by * 14 + c) * Ncols + col];
    }
    ps2[(size_t)by * Ncols + col] = s;
    pq2[(size_t)by * Ncols + col] = q;
}

// ---------------------------------------------------------------- BN finalize (nch chunks)
__global__ void __launch_bounds__(256) bn_finalize(
    const float* __restrict__ ps, const float* __restrict__ pq,
    const float* __restrict__ g, const float* __restrict__ b,
    float* __restrict__ scale, float* __restrict__ shift,
    int Ncols, int nch, float invM)
{
    const int col = blockIdx.x * 256 + threadIdx.x;
    float s = 0.f, s2 = 0.f;
    for (int c = 0; c < nch; c++) {
        s  += ps[(size_t)c * Ncols + col];
        s2 += pq[(size_t)c * Ncols + col];
    }
    float m   = s * invM;
    float var = s2 * invM - m * m;
    float sc  = g[col] * rsqrtf(var + EPSV);
    scale[col] = sc;
    shift[col] = b[col] - m * sc;
}

// ---------------------------------------------------------------- K/V prep (raw fp16 split + transpose) + fused column stats
__global__ void __launch_bounds__(256) prep_kv(
    const float* __restrict__ Ykv,
    __half* __restrict__ KH, __half* __restrict__ KL,
    __half* __restrict__ VTH, __half* __restrict__ VTL,
    float* __restrict__ ps, float* __restrict__ pq)
{
    __shared__ __align__(16) __half sVh[64 * 56];
    __shared__ __align__(16) __half sVl[64 * 56];
    __shared__ float pS[10][96], pQ[10][96];

    const int tid = threadIdx.x;
    const int kc = blockIdx.x, h = blockIdx.y, b = blockIdx.z;
    const int kb = kc * 56;
    const int bh = b * HH + h;

    const int f = tid % 24;
    const int rg = tid / 24;

    if (rg < 10) {
        float s4[4] = {0.f, 0.f, 0.f, 0.f};
        float q4[4] = {0.f, 0.f, 0.f, 0.f};
        for (int r = rg; r < 56; r += 10) {
            float4 v = *(reinterpret_cast<const float4*>(
                Ykv + (size_t)(b * NN + kb + r) * OKV + h * 96) + f);
            float vv[4] = {v.x, v.y, v.z, v.w};
            #pragma unroll
            for (int j = 0; j < 4; j++) {
                s4[j] += vv[j];
                q4[j] = fmaf(vv[j], vv[j], q4[j]);
            }
            if (f < 8) {
                int d = f * 4;
                __half hh[4], ll[4];
                #pragma unroll
                for (int j = 0; j < 4; j++) {
                    hh[j] = __float2half(vv[j]);
                    ll[j] = __float2half(vv[j] - __half2float(hh[j]));
                }
                size_t base = ((size_t)bh * NN + kb + r) * 32 + d;
                reinterpret_cast<__half2*>(KH + base)[0] = __halves2half2(hh[0], hh[1]);
                reinterpret_cast<__half2*>(KH + base)[1] = __halves2half2(hh[2], hh[3]);
                reinterpret_cast<__half2*>(KL + base)[0] = __halves2half2(ll[0], ll[1]);
                reinterpret_cast<__half2*>(KL + base)[1] = __halves2half2(ll[2], ll[3]);
            } else {
                int d = (f - 8) * 4;
                #pragma unroll
                for (int j = 0; j < 4; j++) {
                    __half hh = __float2half(vv[j]);
                    sVh[(d + j) * 56 + r] = hh;
                    sVl[(d + j) * 56 + r] = __float2half(vv[j] - __half2float(hh));
                }
            }
        }
        #pragma unroll
        for (int j = 0; j < 4; j++) { pS[rg][f * 4 + j] = s4[j]; pQ[rg][f * 4 + j] = q4[j]; }
    }
    __syncthreads();

    if (tid < 96) {
        float s = 0.f, q = 0.f;
        #pragma unroll
        for (int gi = 0; gi < 10; gi++) { s += pS[gi][tid]; q += pQ[gi][tid]; }
        size_t chunk = (size_t)(b * 14 + kc);
        ps[chunk * OKV + h * 96 + tid] = s;
        pq[chunk * OKV + h * 96 + tid] = q;
    }

    for (int u = tid; u < 64 * 7; u += 256) {
        int d = u / 7, seg = u - d * 7;
        uint4 vh = *reinterpret_cast<const uint4*>(&sVh[d * 56 + seg * 8]);
        uint4 vl = *reinterpret_cast<const uint4*>(&sVl[d * 56 + seg * 8]);
        size_t base = ((size_t)bh * 64 + d) * NN + kb + seg * 8;
        *reinterpret_cast<uint4*>(VTH + base) = vh;
        *reinterpret_cast<uint4*>(VTL + base) = vl;
    }
}

// ---------------------------------------------------------------- attention (tensor-core, raw K/V, folded BN)
__device__ __forceinline__ float hswish(float x) {
    float t = fminf(fmaxf(x + 3.f, 0.f), 6.f);
    return x * t * (1.f / 6.f);
}

// smem byte offsets
#define AQP 80
#define AVP 144
#define K_ST 4480
#define V_ST 9216
#define O_QH 0
#define O_QL 5120
#define O_KH 10240
#define O_KL 19200
#define O_VH 28160
#define O_VL 46592
#define O_PH 65024
#define O_PL 74240
#define O_S  83456
#define O_BH 94432
#define O_SCQ 97568
#define O_SHQ 97696
#define O_SCK 97824
#define O_SCV 97952
#define O_SHV 98208
#define O_MR 98464
#define O_LR 98720
#define O_AR 98976
#define ATTN_SMEM 99232

__global__ void __launch_bounds__(256) attn_mma2(
    const __half* __restrict__ KHg, const __half* __restrict__ KLg,
    const __half* __restrict__ VTHg, const __half* __restrict__ VTLg,
    const float* __restrict__ Yq,
    const float* __restrict__ scq,  const float* __restrict__ shq,
    const float* __restrict__ sckv, const float* __restrict__ shkv,
    const float* __restrict__ biases, const int* __restrict__ bidx,
    __half* __restrict__ Yoh, __half* __restrict__ Yol)
{
    extern __shared__ char sm[];
    __half* Qh = reinterpret_cast<__half*>(sm + O_QH);
    __half* Ql = reinterpret_cast<__half*>(sm + O_QL);
    __half* Ph = reinterpret_cast<__half*>(sm + O_PH);
    __half* Pl = reinterpret_cast<__half*>(sm + O_PL);
    float* S    = reinterpret_cast<float*>(sm + O_S);
    float* bh   = reinterpret_cast<float*>(sm + O_BH);
    float* scqh = reinterpret_cast<float*>(sm + O_SCQ);
    float* shqh = reinterpret_cast<float*>(sm + O_SHQ);
    float* sckh = reinterpret_cast<float*>(sm + O_SCK);
    float* scvh = reinterpret_cast<float*>(sm + O_SCV);
    float* shvh = reinterpret_cast<float*>(sm + O_SHV);
    float* mrow = reinterpret_cast<float*>(sm + O_MR);
    float* lrow = reinterpret_cast<float*>(sm + O_LR);
    float* arow = reinterpret_cast<float*>(sm + O_AR);

    const int tid = threadIdx.x;
    const int wid = tid >> 5, lane = tid & 31;
    const int qg = blockIdx.x, h = blockIdx.y, b = blockIdx.z;
    const int bh_idx = b * HH + h;

    const __half* KHb = KHg + (size_t)bh_idx * NN * 32;
    const __half* KLb = KLg + (size_t)bh_idx * NN * 32;
    const __half* VHb = VTHg + (size_t)bh_idx * 64 * NN;
    const __half* VLb = VTLg + (size_t)bh_idx * 64 * NN;

    const uint32_t sbase = smem_u32(sm);
    const uint32_t uQH = sbase + O_QH, uQL = sbase + O_QL;
    const uint32_t uKH = sbase + O_KH, uKL = sbase + O_KL;
    const uint32_t uVH = sbase + O_VH, uVL = sbase + O_VL;
    const uint32_t uPH = sbase + O_PH, uPL = sbase + O_PL;

    if (tid < 32) {
        scqh[tid] = scq[h * 32 + tid];
        shqh[tid] = shq[h * 32 + tid];
        sckh[tid] = sckv[h * 96 + tid];
    } else if (tid < 96) {
        int d = tid - 32;
        scvh[d] = sckv[h * 96 + 32 + d];
        shvh[d] = shkv[h * 96 + 32 + d];
    }
    for (int i = tid; i < 784; i += 256) bh[i] = biases[h * 784 + i];
    if (tid < 64) { mrow[tid] = -1e30f; lrow[tid] = 0.f; arow[tid] = 0.f; }
    for (int u = tid; u < 150; u += 256) {
        int m = u / 75, w = u - m * 75;
        int r = 49 + w / 5, sgm = w - (w / 5) * 5;
        uint32_t off = (m == 0 ? O_QH : O_QL) + (uint32_t)r * AQP + sgm * 16;
        *reinterpret_cast<uint4*>(sm + off) = make_uint4(0, 0, 0, 0);
    }
    for (int u = tid; u < 512; u += 256) {
        int m = u >> 8, w = u & 255;
        int st = w >> 7, w2 = w & 127;
        int d = w2 >> 1, half = w2 & 1;
        uint32_t off = (m == 0 ? O_VH : O_VL) + st * V_ST + (uint32_t)d * AVP + 112 + half * 16;
        *reinterpret_cast<uint4*>(sm + off) = make_uint4(0, 0, 0, 0);
    }
    for (int u = tid; u < 1152; u += 256)
        reinterpret_cast<uint4*>(sm + O_PH)[u] = make_uint4(0, 0, 0, 0);
    __syncthreads();

    for (int e = tid; e < 49 * 32; e += 256) {
        int r = e >> 5, d = e & 31;
        float v = fmaf(Yq[(size_t)(b * NQ + qg * 49 + r) * OQ + h * 32 + d], scqh[d], shqh[d]) * sckh[d];
        __half hh = __float2half(v);
        Qh[r * 40 + d] = hh;
        Ql[r * 40 + d] = __float2half(v - __half2float(hh));
    }

    auto issue_chunk = [&](int kc) {
        const int st = kc & 1;
        const int kb = kc * 56;
        #pragma unroll
        for (int i = 0; i < 6; i++) {
            int u = tid + i * 256;
            if (u >= 1344) break;
            if (u < 448) {
                int hi = (u < 224);
                int w = hi ? u : u - 224;
                int r = w >> 2, seg = w & 3;
                const __half* src = (hi ? KHb : KLb) + (size_t)(kb + r) * 32 + seg * 8;
                uint32_t dst = (hi ? uKH : uKL) + st * K_ST + (uint32_t)r * AQP + seg * 16;
                cp_async16(dst, src);
            } else {
                int v = u - 448;
                int hi = (v < 448);
                int w = hi ? v : v - 448;
                int d = w / 7, seg = w - d * 7;
                const __half* src = (hi ? VHb : VLb) + (size_t)d * NN + kb + seg * 8;
                uint32_t dst = (hi ? uVH : uVL) + st * V_ST + (uint32_t)d * AVP + seg * 16;
                cp_async16(dst, src);
            }
        }
        cp_commit();
    };

    const int mw  = wid >> 1;
    const int nt0 = (wid & 1) * 4;
    const int ntn = (wid & 1) ? 3 : 4;
    const int g   = lane >> 2, t4 = lane & 3;
    const int sub = lane >> 3;
    const int arow_f = (lane & 7) + ((sub & 1) << 3);
    const int akof   = (sub >> 1) << 3;
    const int brow_f = lane & 7;
    const int bkof   = ((lane >> 3) & 1) << 3;
    const int sr = (tid < 196) ? (tid >> 2) : 48;
    const int sq = tid & 3;
    const bool sact = (tid < 196);

    float accp[4][4];
    #pragma unroll
    for (int i = 0; i < 4; i++)
        #pragma unroll
        for (int j = 0; j < 4; j++) accp[i][j] = 0.f;

    issue_chunk(0);

    for (int kc = 0; kc < 14; kc++) {
        const int st = kc & 1;
        const int kb = kc * 56;

        cp_wait<0>();
        __syncthreads();

        if (kc + 1 < 14) issue_chunk(kc + 1);

        // ---- QK mma + bias + write S
        {
            float acc[4][4];
            #pragma unroll
            for (int i = 0; i < 4; i++)
                #pragma unroll
                for (int j = 0; j < 4; j++) acc[i][j] = 0.f;
            #pragma unroll
            for (int ks = 0; ks < 2; ks++) {
                uint32_t aoff = (uint32_t)(mw * 16 + arow_f) * AQP + (uint32_t)(ks * 16 + akof) * 2;
                uint32_t Ahf[4], Alf[4];
                ldsm_x4(uQH + aoff, Ahf[0], Ahf[1], Ahf[2], Ahf[3]);
                ldsm_x4(uQL + aoff, Alf[0], Alf[1], Alf[2], Alf[3]);
                for (int nti = 0; nti < ntn; nti++) {
                    int nt = nt0 + nti;
                    uint32_t boff = st * K_ST + (uint32_t)(nt * 8 + brow_f) * AQP
                                  + (uint32_t)(ks * 16 + bkof) * 2;
                    uint32_t bh0, bh1, bl0, bl1;
                    ldsm_x2(uKH + boff, bh0, bh1);
                    ldsm_x2(uKL + boff, bl0, bl1);
                    mma16816(acc[nti], Ahf[0], Ahf[1], Ahf[2], Ahf[3], bh0, bh1);
                    mma16816(acc[nti], Ahf[0], Ahf[1], Ahf[2], Ahf[3], bl0, bl1);
                    mma16816(acc[nti], Alf[0], Alf[1], Alf[2], Alf[3], bh0, bh1);
                }
            }
            const int r0 = mw * 16 + g;
            for (int nti = 0; nti < ntn; nti++) {
                int nt = nt0 + nti;
                int c0 = nt * 8 + t4 * 2;
                if (r0 < 49) {
                    int2 id = *reinterpret_cast<const int2*>(
                        &bidx[(size_t)(qg * 49 + r0) * NN + kb + c0]);
                    float2 s0 = make_float2(fmaf(acc[nti][0], SCALE_QK, bh[id.x]),
                                            fmaf(acc[nti][1], SCALE_QK, bh[id.y]));
                    *reinterpret_cast<float2*>(&S[r0 * 56 + c0]) = s0;
                }
                if (r0 + 8 < 49) {
                    int2 id = *reinterpret_cast<const int2*>(
                        &bidx[(size_t)(qg * 49 + r0 + 8) * NN + kb + c0]);
                    float2 s1 = make_float2(fmaf(acc[nti][2], SCALE_QK, bh[id.x]),
                                            fmaf(acc[nti][3], SCALE_QK, bh[id.y]));
                    *reinterpret_cast<float2*>(&S[(r0 + 8) * 56 + c0]) = s1;
                }
            }
        }
        __syncthreads();

        // ---- online softmax, write P fp16 hi/lo
        {
            float xv[14];
            float cm = -1e30f;
            #pragma unroll
            for (int j = 0; j < 14; j++) {
                xv[j] = S[sr * 56 + sq + 4 * j];
                cm = fmaxf(cm, xv[j]);
            }
            cm = fmaxf(cm, __shfl_xor_sync(0xffffffffu, cm, 1));
            cm = fmaxf(cm, __shfl_xor_sync(0xffffffffu, cm, 2));
            float mo = mrow[sr];
            float mn = fmaxf(mo, cm);
            float cs = 0.f;
            #pragma unroll
            for (int j = 0; j < 14; j++) {
                float p = __expf(xv[j] - mn);
                xv[j] = p;
                cs += p;
            }
            cs += __shfl_xor_sync(0xffffffffu, cs, 1);
            cs += __shfl_xor_sync(0xffffffffu, cs, 2);
            if (sact) {
                #pragma unroll
                for (int j = 0; j < 14; j++) {
                    __half ph = __float2half(xv[j]);
                    Ph[sr * 72 + sq + 4 * j] = ph;
                    Pl[sr * 72 + sq + 4 * j] = __float2half(xv[j] - __half2float(ph));
                }
                if (sq == 0) {
                    float a = __expf(mo - mn);
                    arow[sr] = a;
                    lrow[sr] = lrow[sr] * a + cs;
                    mrow[sr] = mn;
                }
            }
        }
        __syncthreads();

        // ---- PV mma with rescale
        {
            const int r0 = mw * 16 + g;
            float a0 = arow[r0], a1 = arow[r0 + 8];
            #pragma unroll
            for (int nti = 0; nti < 4; nti++) {
                accp[nti][0] *= a0; accp[nti][1] *= a0;
                accp[nti][2] *= a1; accp[nti][3] *= a1;
            }
            #pragma unroll
            for (int ks = 0; ks < 4; ks++) {
                uint32_t aoff = (uint32_t)(mw * 16 + arow_f) * AVP + (uint32_t)(ks * 16 + akof) * 2;
                uint32_t Phf[4], Plf[4];
                ldsm_x4(uPH + aoff, Phf[0], Phf[1], Phf[2], Phf[3]);
                ldsm_x4(uPL + aoff, Plf[0], Plf[1], Plf[2], Plf[3]);
                #pragma unroll
                for (int nti = 0; nti < 4; nti++) {
                    int dt8 = ((wid & 1) * 4 + nti) * 8;
                    uint32_t boff = st * V_ST + (uint32_t)(dt8 + brow_f) * AVP
                                  + (uint32_t)(ks * 16 + bkof) * 2;
                    uint32_t vh0, vh1, vl0, vl1;
                    ldsm_x2(uVH + boff, vh0, vh1);
                    ldsm_x2(uVL + boff, vl0, vl1);
                    mma16816(accp[nti], Phf[0], Phf[1], Phf[2], Phf[3], vh0, vh1);
                    mma16816(accp[nti], Phf[0], Phf[1], Phf[2], Phf[3], vl0, vl1);
                    mma16816(accp[nti], Plf[0], Plf[1], Plf[2], Plf[3], vh0, vh1);
                }
            }
        }
    }

    // ---- epilogue: out = hswish(scv * acc/l + shv), fp16 hi/lo store
    const int r0 = mw * 16 + g;
    #pragma unroll
    for (int half = 0; half < 2; half++) {
        int rr = r0 + half * 8;
        if (rr >= 49) continue;
        float inv = 1.0f / lrow[rr];
        int q = qg * 49 + rr;
        #pragma unroll
        for (int nti = 0; nti < 4; nti++) {
            int c0 = (wid & 1) * 32 + nti * 8 + t4 * 2;
            float o0 = hswish(fmaf(accp[nti][half * 2 + 0] * inv, scvh[c0],     shvh[c0]));
            float o1 = hswish(fmaf(accp[nti][half * 2 + 1] * inv, scvh[c0 + 1], shvh[c0 + 1]));
            __half h0 = __float2half(o0);
            __half h1 = __float2half(o1);
            __half l0 = __float2half(o0 - __half2float(h0));
            __half l1 = __float2half(o1 - __half2float(h1));
            size_t base = (size_t)(b * NQ + q) * DH + h * 64 + c0;
            *reinterpret_cast<__half2*>(Yoh + base) = __halves2half2(h0, h1);
            *reinterpret_cast<__half2*>(Yol + base) = __halves2half2(l0, l1);
        }
    }
}

// ---------------------------------------------------------------- final BN apply (float4)
__global__ void __launch_bounds__(256) bn_apply4(
    const float4* __restrict__ Y, const float* __restrict__ scale,
    const float* __restrict__ shift, float4* __restrict__ out, int Ncols4)
{
    const int i = blockIdx.x * 256 + threadIdx.x;
    float4 v = Y[i];
    const int c = (i % Ncols4) * 4;
    out[i] = make_float4(fmaf(v.x, scale[c + 0], shift[c + 0]),
                         fmaf(v.y, scale[c + 1], shift[c + 1]),
                         fmaf(v.z, scale[c + 2], shift[c + 2]),
                         fmaf(v.w, scale[c + 3], shift[c + 3]));
}

// ---------------------------------------------------------------- launch
extern "C" void kernel_launch(void* const* d_in, const int* in_sizes, int n_in,
                              void* d_out, int out_size)
{
    const float* x    = (const float*)d_in[0];
    const float* W_kv = (const float*)d_in[1];
    const float* gkv  = (const float*)d_in[2];
    const float* bkv  = (const float*)d_in[3];
    const float* W_q  = (const float*)d_in[4];
    const float* gq   = (const float*)d_in[5];
    const float* bq   = (const float*)d_in[6];
    const float* W_p  = (const float*)d_in[7];
    const float* gp   = (const float*)d_in[8];
    const float* bp   = (const float*)d_in[9];
    const float* ab   = (const float*)d_in[10];
    const int*   bidx = (const int*)d_in[11];
    float* out = (float*)d_out;

    float *Ykv, *Yq, *Yp, *ps, *pq, *ps2, *pq2;
    float *sckv, *shkv, *scq, *shq, *scp, *shp;
    __half *xh, *xl, *Wkvh, *Wkvl, *Wqh, *Wql, *Wph, *Wpl, *Yoh, *Yol;
    __half *KH, *KL, *VTH, *VTL;
    cudaGetSymbolAddress((void**)&Ykv, g_Ykv);
    cudaGetSymbolAddress((void**)&Yq,  g_Yq);
    cudaGetSymbolAddress((void**)&Yp,  g_Yp);
    cudaGetSymbolAddress((void**)&ps,  g_ps);
    cudaGetSymbolAddress((void**)&pq,  g_pq);
    cudaGetSymbolAddress((void**)&ps2, g_ps2);
    cudaGetSymbolAddress((void**)&pq2, g_pq2);
    cudaGetSymbolAddress((void**)&sckv, g_sc_kv);
    cudaGetSymbolAddress((void**)&shkv, g_sh_kv);
    cudaGetSymbolAddress((void**)&scq,  g_sc_q);
    cudaGetSymbolAddress((void**)&shq,  g_sh_q);
    cudaGetSymbolAddress((void**)&scp,  g_sc_p);
    cudaGetSymbolAddress((void**)&shp,  g_sh_p);
    cudaGetSymbolAddress((void**)&xh,   g_xh);
    cudaGetSymbolAddress((void**)&xl,   g_xl);
    cudaGetSymbolAddress((void**)&Wkvh, g_Wkvh);
    cudaGetSymbolAddress((void**)&Wkvl, g_Wkvl);
    cudaGetSymbolAddress((void**)&Wqh,  g_Wqh);
    cudaGetSymbolAddress((void**)&Wql,  g_Wql);
    cudaGetSymbolAddress((void**)&Wph,  g_Wph);
    cudaGetSymbolAddress((void**)&Wpl,  g_Wpl);
    cudaGetSymbolAddress((void**)&Yoh,  g_Yoh);
    cudaGetSymbolAddress((void**)&Yol,  g_Yol);
    cudaGetSymbolAddress((void**)&KH,   g_KH);
    cudaGetSymbolAddress((void**)&KL,   g_KL);
    cudaGetSymbolAddress((void**)&VTH,  g_VTH);
    cudaGetSymbolAddress((void**)&VTL,  g_VTL);

    cudaFuncSetAttribute((const void*)gemm_mma<0,1>, cudaFuncAttributeMaxDynamicSharedMemorySize, GEMM_SMEM);
    cudaFuncSetAttribute((const void*)gemm_mma<0,2>, cudaFuncAttributeMaxDynamicSharedMemorySize, GEMM_SMEM);
    cudaFuncSetAttribute((const void*)gemm_mma<1,2>, cudaFuncAttributeMaxDynamicSharedMemorySize, GEMM_SMEM);
    cudaFuncSetAttribute(attn_mma2, cudaFuncAttributeMaxDynamicSharedMemorySize, ATTN_SMEM);

    // 0) fp16 hi/lo splits
    cvt_split4<<<(unsigned)(((size_t)MKV * CC / 4 + 255) / 256), 256>>>(x, xh, xl, (size_t)MKV * CC / 4);
    cvt_split4<<<(unsigned)(((size_t)OKV * CC / 4 + 255) / 256), 256>>>(W_kv, Wkvh, Wkvl, (size_t)OKV * CC / 4);
    cvt_split4<<<(unsigned)(((size_t)OQ  * CC / 4 + 255) / 256), 256>>>(W_q, Wqh, Wql, (size_t)OQ * CC / 4);
    cvt_split4<<<(unsigned)(((size_t)OP  * DH / 4 + 255) / 256), 256>>>(W_p, Wph, Wpl, (size_t)OP * DH / 4);

    // 1) kv GEMM (1-pass fp16) ; prep ; reduce ; BN finalize
    gemm_mma<0,1><<<dim3(OKV / 128, MKV / 128), 256, GEMM_SMEM>>>(xh, xl, Wkvh, Wkvl, Ykv, MKV, OKV, CC);
    prep_kv<<<dim3(14, HH, BB), 256>>>(Ykv, KH, KL, VTH, VTL, ps, pq);
    reduce14<<<dim3(OKV / 256, 64), 256>>>(ps, pq, ps2, pq2, OKV);
    bn_finalize<<<OKV / 256, 256>>>(ps2, pq2, gkv, bkv, sckv, shkv, OKV, 64, 1.f / MKV);

    // 2) q = xq @ W_q^T (gathered rows, 2-pass fp16)
    gemm_mma<1,2><<<dim3(OQ / 128, MQ / 128), 256, GEMM_SMEM>>>(xh, xl, Wqh, Wql, Yq, MQ, OQ, CC);
    col_partial<<<dim3(OQ / 256, 64), 256>>>(Yq, ps, pq, MQ, OQ);
    bn_finalize<<<OQ / 256, 256>>>(ps, pq, gq, bq, scq, shq, OQ, 64, 1.f / MQ);

    // 3) attention + hard-swish
    attn_mma2<<<dim3(4, HH, BB), 256, ATTN_SMEM>>>(
        KH, KL, VTH, VTL, Yq, scq, shq, sckv, shkv, ab, bidx, Yoh, Yol);

    // 4) proj (2-pass fp16)
    gemm_mma<0,2><<<dim3(OP / 128, MQ / 128), 256, GEMM_SMEM>>>(Yoh, Yol, Wph, Wpl, Yp, MQ, OP, DH);
    col_partial<<<dim3(OP / 256, 64), 256>>>(Yp, ps, pq, MQ, OP);
    bn_finalize<<<OP / 256, 256>>>(ps, pq, gp, bp, scp, shp, OP, 64, 1.f / MQ);
    bn_apply4<<<(MQ * OP / 4) / 256, 256>>>(
        reinterpret_cast<const float4*>(Yp), scp, shp,
        reinterpret_cast<float4*>(out), OP / 4);
}